// round 8
// baseline (speedup 1.0000x reference)
#include <cuda_runtime.h>
#include <cuda_bf16.h>
#include <cstdint>

// ---------------------------------------------------------------------------
// GraphSAGE (3x SAGEConv + BN/ReLU) on B200 / sm_100a.
//   - Layer-0 GEMM split in two this round: x@Wr0 runs BEFORE the CSR build
//     (launch index 3) so ncu's fixed sample window lands on a GEMM -> next
//     round gets a real tensor-pipe measurement. agg@Wl0 then accumulates.
//   - Layer-1 aggregation gathers bf16 act0(h1); fp32 accumulate.
//   - GEMM: TF32 mma.sync m16n8k8, dual-A fusion, double-buffered dyn smem.
//   - Layer 2 trick: mean_agg(act(h2)) @ Wl2 == mean_agg(act(h2) @ Wl2).
// ---------------------------------------------------------------------------

#define NNODES 50000
#define NEDGES 1600000
#define INDIM  128
#define HIDDIM 256
#define OUTDIM 64
#define NB_STATS 512

// ------------------------- scratch (device globals) ------------------------
__device__ float g_agg[(size_t)NNODES * HIDDIM];
__device__ float g_h1 [(size_t)NNODES * HIDDIM];
__device__ float g_h2 [(size_t)NNODES * HIDDIM];
__device__ float g_y  [(size_t)NNODES * OUTDIM];
__device__ __align__(16) __nv_bfloat16 g_h1b[(size_t)NNODES * HIDDIM];
__device__ float g_invdeg[NNODES];
__device__ int   g_cnt[NNODES];
__device__ int   g_rowptr[NNODES + 1];
__device__ int   g_fill[NNODES];
__device__ int   g_csr[NEDGES];
__device__ float g_ps[NB_STATS * HIDDIM];
__device__ float g_pq[NB_STATS * HIDDIM];
__device__ __align__(16) float g_scale[HIDDIM];
__device__ __align__(16) float g_shift[HIDDIM];

// ------------------------------- CSR build ---------------------------------
__global__ void zero_int_kernel(int* p, int n) {
    int i = blockIdx.x * blockDim.x + threadIdx.x;
    if (i < n) p[i] = 0;
}

__global__ void hist_kernel(const int* __restrict__ ei, int ne, int* __restrict__ cnt) {
    int e = blockIdx.x * blockDim.x + threadIdx.x;
    if (e < ne) {
        int d = ei[ne + e];
        if ((unsigned)d < (unsigned)NNODES)
            atomicAdd(&cnt[d], 1);
    }
}

__global__ void scan_prep_kernel(const int* __restrict__ cnt, int* __restrict__ rowptr,
                                 int* __restrict__ fill, float* __restrict__ invdeg, int n) {
    __shared__ int wsum[32];
    __shared__ int carry_s;
    int tid = threadIdx.x, lane = tid & 31, wid = tid >> 5;
    if (tid == 0) { carry_s = 0; rowptr[0] = 0; }
    __syncthreads();
    for (int base = 0; base < n; base += 1024) {
        int i = base + tid;
        int v = (i < n) ? cnt[i] : 0;
        int s = v;
#pragma unroll
        for (int off = 1; off < 32; off <<= 1) {
            int t = __shfl_up_sync(0xffffffffu, s, off);
            if (lane >= off) s += t;
        }
        if (lane == 31) wsum[wid] = s;
        __syncthreads();
        if (wid == 0) {
            int w = wsum[lane];
#pragma unroll
            for (int off = 1; off < 32; off <<= 1) {
                int t = __shfl_up_sync(0xffffffffu, w, off);
                if (lane >= off) w += t;
            }
            wsum[lane] = w;
        }
        __syncthreads();
        int incl = s + (wid ? wsum[wid - 1] : 0) + carry_s;
        if (i < n) {
            rowptr[i + 1] = incl;
            fill[i] = incl - v;
            invdeg[i] = 1.0f / (float)(v > 0 ? v : 1);
        }
        __syncthreads();
        if (tid == 1023) carry_s = incl;
        __syncthreads();
    }
}

__global__ void scatter_kernel(const int* __restrict__ ei, int ne,
                               int* __restrict__ fill, int* __restrict__ csr) {
    int e = blockIdx.x * blockDim.x + threadIdx.x;
    if (e < ne) {
        int s = ei[e];
        int d = ei[ne + e];
        if ((unsigned)d < (unsigned)NNODES && (unsigned)s < (unsigned)NNODES) {
            int pos = atomicAdd(&fill[d], 1);
            if ((unsigned)pos < (unsigned)NEDGES)
                csr[pos] = s;
        }
    }
}

// ------------------------- act -> bf16 conversion ---------------------------
__global__ void act_bf16_kernel(const float4* __restrict__ H, __nv_bfloat162* __restrict__ O2,
                                int n4, const float* __restrict__ sc, const float* __restrict__ sh) {
    int i = blockIdx.x * blockDim.x + threadIdx.x;
    if (i >= n4) return;
    int c = (i * 4) & (HIDDIM - 1);
    float4 v = H[i];
    v.x = fmaxf(v.x * __ldg(sc + c + 0) + __ldg(sh + c + 0), 0.f);
    v.y = fmaxf(v.y * __ldg(sc + c + 1) + __ldg(sh + c + 1), 0.f);
    v.z = fmaxf(v.z * __ldg(sc + c + 2) + __ldg(sh + c + 2), 0.f);
    v.w = fmaxf(v.w * __ldg(sc + c + 3) + __ldg(sh + c + 3), 0.f);
    O2[i * 2 + 0] = __floats2bfloat162_rn(v.x, v.y);
    O2[i * 2 + 1] = __floats2bfloat162_rn(v.z, v.w);
}

// ------------------------- bf16 aggregation (D=256) -------------------------
__global__ void agg256_bf16_kernel(const __nv_bfloat16* __restrict__ Xb, float* __restrict__ Out,
                                   const int* __restrict__ rowptr, const int* __restrict__ csr,
                                   const float* __restrict__ invdeg, int n_nodes) {
    int node = (blockIdx.x * blockDim.x + threadIdx.x) >> 5;
    if (node >= n_nodes) return;
    int lane = threadIdx.x & 31;
    int doff = lane * 8;

    float acc0[8], acc1[8];
#pragma unroll
    for (int i = 0; i < 8; i++) { acc0[i] = 0.f; acc1[i] = 0.f; }

    int beg = rowptr[node];
    int end = rowptr[node + 1];
    int e = beg;

    auto accum = [&](uint4 u, float* acc) {
        __nv_bfloat162 b0 = *reinterpret_cast<__nv_bfloat162*>(&u.x);
        __nv_bfloat162 b1 = *reinterpret_cast<__nv_bfloat162*>(&u.y);
        __nv_bfloat162 b2 = *reinterpret_cast<__nv_bfloat162*>(&u.z);
        __nv_bfloat162 b3 = *reinterpret_cast<__nv_bfloat162*>(&u.w);
        float2 f0 = __bfloat1622float2(b0);
        float2 f1 = __bfloat1622float2(b1);
        float2 f2 = __bfloat1622float2(b2);
        float2 f3 = __bfloat1622float2(b3);
        acc[0] += f0.x; acc[1] += f0.y;
        acc[2] += f1.x; acc[3] += f1.y;
        acc[4] += f2.x; acc[5] += f2.y;
        acc[6] += f3.x; acc[7] += f3.y;
    };

    for (; e + 3 < end; e += 4) {
        int s0 = __ldg(csr + e);
        int s1 = __ldg(csr + e + 1);
        int s2 = __ldg(csr + e + 2);
        int s3 = __ldg(csr + e + 3);
        uint4 u0 = __ldg(reinterpret_cast<const uint4*>(Xb + (size_t)s0 * HIDDIM + doff));
        uint4 u1 = __ldg(reinterpret_cast<const uint4*>(Xb + (size_t)s1 * HIDDIM + doff));
        uint4 u2 = __ldg(reinterpret_cast<const uint4*>(Xb + (size_t)s2 * HIDDIM + doff));
        uint4 u3 = __ldg(reinterpret_cast<const uint4*>(Xb + (size_t)s3 * HIDDIM + doff));
        accum(u0, acc0); accum(u1, acc1); accum(u2, acc0); accum(u3, acc1);
    }
    for (; e < end; e++) {
        int s0 = __ldg(csr + e);
        uint4 u0 = __ldg(reinterpret_cast<const uint4*>(Xb + (size_t)s0 * HIDDIM + doff));
        accum(u0, acc0);
    }

    float w = __ldg(invdeg + node);
    float* o = Out + (size_t)node * HIDDIM + doff;
    float4 o0 = make_float4((acc0[0] + acc1[0]) * w, (acc0[1] + acc1[1]) * w,
                            (acc0[2] + acc1[2]) * w, (acc0[3] + acc1[3]) * w);
    float4 o1 = make_float4((acc0[4] + acc1[4]) * w, (acc0[5] + acc1[5]) * w,
                            (acc0[6] + acc1[6]) * w, (acc0[7] + acc1[7]) * w);
    *reinterpret_cast<float4*>(o)     = o0;
    *reinterpret_cast<float4*>(o + 4) = o1;
}

// ------------------------ fp32 aggregation (D=64/128) -----------------------
template <int D, bool ADD>
__global__ void agg_kernel(const float* __restrict__ X, float* __restrict__ Out,
                           const int* __restrict__ rowptr, const int* __restrict__ csr,
                           const float* __restrict__ invdeg, int n_nodes) {
    constexpr int PL = D / 32;
    int node = (blockIdx.x * blockDim.x + threadIdx.x) >> 5;
    if (node >= n_nodes) return;
    int lane = threadIdx.x & 31;
    int doff = lane * PL;

    float acc0[PL], acc1[PL];
#pragma unroll
    for (int i = 0; i < PL; i++) { acc0[i] = 0.f; acc1[i] = 0.f; }

    int beg = rowptr[node];
    int end = rowptr[node + 1];
    int e = beg;

    if constexpr (PL == 4) {
        for (; e + 3 < end; e += 4) {
            int s0 = __ldg(csr + e);
            int s1 = __ldg(csr + e + 1);
            int s2 = __ldg(csr + e + 2);
            int s3 = __ldg(csr + e + 3);
            float4 v0 = __ldg(reinterpret_cast<const float4*>(X + (size_t)s0 * D + doff));
            float4 v1 = __ldg(reinterpret_cast<const float4*>(X + (size_t)s1 * D + doff));
            float4 v2 = __ldg(reinterpret_cast<const float4*>(X + (size_t)s2 * D + doff));
            float4 v3 = __ldg(reinterpret_cast<const float4*>(X + (size_t)s3 * D + doff));
            acc0[0] += v0.x + v2.x;  acc1[0] += v1.x + v3.x;
            acc0[1] += v0.y + v2.y;  acc1[1] += v1.y + v3.y;
            acc0[2] += v0.z + v2.z;  acc1[2] += v1.z + v3.z;
            acc0[3] += v0.w + v2.w;  acc1[3] += v1.w + v3.w;
        }
        for (; e < end; e++) {
            int s0 = __ldg(csr + e);
            float4 v0 = __ldg(reinterpret_cast<const float4*>(X + (size_t)s0 * D + doff));
            acc0[0] += v0.x; acc0[1] += v0.y; acc0[2] += v0.z; acc0[3] += v0.w;
        }
    } else {
        for (; e + 3 < end; e += 4) {
            int s0 = __ldg(csr + e);
            int s1 = __ldg(csr + e + 1);
            int s2 = __ldg(csr + e + 2);
            int s3 = __ldg(csr + e + 3);
            float2 v0 = __ldg(reinterpret_cast<const float2*>(X + (size_t)s0 * D + doff));
            float2 v1 = __ldg(reinterpret_cast<const float2*>(X + (size_t)s1 * D + doff));
            float2 v2 = __ldg(reinterpret_cast<const float2*>(X + (size_t)s2 * D + doff));
            float2 v3 = __ldg(reinterpret_cast<const float2*>(X + (size_t)s3 * D + doff));
            acc0[0] += v0.x + v2.x;  acc1[0] += v1.x + v3.x;
            acc0[1] += v0.y + v2.y;  acc1[1] += v1.y + v3.y;
        }
        for (; e < end; e++) {
            int s0 = __ldg(csr + e);
            float2 v0 = __ldg(reinterpret_cast<const float2*>(X + (size_t)s0 * D + doff));
            acc0[0] += v0.x; acc0[1] += v0.y;
        }
    }

    float w = __ldg(invdeg + node);
    float* o = Out + (size_t)node * D + doff;
#pragma unroll
    for (int i = 0; i < PL; i++) {
        float a = (acc0[i] + acc1[i]) * w;
        if constexpr (ADD) o[i] += a;
        else               o[i]  = a;
    }
}

// ------------------------------ TF32 GEMM -----------------------------------
__device__ __forceinline__ unsigned f2tf32(float f) {
    unsigned u;
    asm("cvt.rna.tf32.f32 %0, %1;" : "=r"(u) : "f"(f));
    return u;
}

__device__ __forceinline__ void mma_tf32(float c[4], const unsigned a[4], const unsigned b[2]) {
    asm volatile(
        "mma.sync.aligned.m16n8k8.row.col.f32.tf32.tf32.f32 "
        "{%0,%1,%2,%3}, {%4,%5,%6,%7}, {%8,%9}, {%0,%1,%2,%3};"
        : "+f"(c[0]), "+f"(c[1]), "+f"(c[2]), "+f"(c[3])
        : "r"(a[0]), "r"(a[1]), "r"(a[2]), "r"(a[3]), "r"(b[0]), "r"(b[1]));
}

// C = act0(A0)@B0 (+ act1(A1)@B1) (+ bias) (+ C if accumulate). Dyn smem, 2-buf.
template <int BM, int BN, int WM, int WN>
__global__ void gemm_tf32(const float* __restrict__ A0, const float* __restrict__ B0g,
                          const float* __restrict__ sc0, const float* __restrict__ sh0,
                          const float* __restrict__ A1, const float* __restrict__ B1g,
                          const float* __restrict__ sc1, const float* __restrict__ sh1,
                          float* __restrict__ C, int M, int N, int K,
                          const float* __restrict__ bias, int accumulate) {
    constexpr int BK = 32, THREADS = 256;
    constexpr int WCOLS = BN / WN;
    constexpr int MT = WM / 16, NT = WN / 8;
    constexpr int ACH = (BM * BK) / (4 * THREADS);
    constexpr int BCH = (BK * BN) / (4 * THREADS);
    constexpr int BROWCH = BN / 4;
    constexpr int ASTRIDE = BM + 1;
    constexpr int BSTRIDE = BN + 4;
    static_assert((BM / WM) * (BN / WN) == 8, "8 warps");

    extern __shared__ unsigned smem_u[];
    unsigned* Asm = smem_u;
    unsigned* Bsm = smem_u + 2 * BK * ASTRIDE;
#define AS(b, k, m) Asm[((b) * BK + (k)) * ASTRIDE + (m)]
#define BS(b, k, n) Bsm[((b) * BK + (k)) * BSTRIDE + (n)]

    int tid = threadIdx.x, lane = tid & 31, warp = tid >> 5;
    int wrow = warp / WCOLS, wcol = warp % WCOLS;
    int block_m = blockIdx.y * BM, block_n = blockIdx.x * BN;
    int g = lane >> 2, q = lane & 3;

    float acc[MT][NT][4];
#pragma unroll
    for (int mt = 0; mt < MT; mt++)
#pragma unroll
        for (int nt = 0; nt < NT; nt++)
#pragma unroll
            for (int r = 0; r < 4; r++) acc[mt][nt][r] = 0.0f;

    const int kiters = K / BK;
    const int npass = A1 ? 2 : 1;
    const int total = npass * kiters;

    float4 ra[ACH], rb[BCH];

    auto load_stage = [&](int it) {
        int pass = it / kiters;
        int k0 = (it - pass * kiters) * BK;
        const float* Ap = pass ? A1 : A0;
        const float* Bp = pass ? B1g : B0g;
#pragma unroll
        for (int i = 0; i < ACH; i++) {
            int chunk = tid + i * THREADS;
            int r = chunk >> 3;
            int c4 = (chunk & 7) << 2;
            int gr = block_m + r;
            float4 v = make_float4(0.f, 0.f, 0.f, 0.f);
            if (gr < M)
                v = *reinterpret_cast<const float4*>(Ap + (size_t)gr * K + k0 + c4);
            ra[i] = v;
        }
#pragma unroll
        for (int i = 0; i < BCH; i++) {
            int chunk = tid + i * THREADS;
            int r = chunk / BROWCH;
            int c4 = (chunk % BROWCH) * 4;
            rb[i] = *reinterpret_cast<const float4*>(Bp + (size_t)(k0 + r) * N + block_n + c4);
        }
    };

    auto store_stage = [&](int it, int buf) {
        int pass = it / kiters;
        int k0 = (it - pass * kiters) * BK;
        const float* sc = pass ? sc1 : sc0;
        const float* sh = pass ? sh1 : sh0;
#pragma unroll
        for (int i = 0; i < ACH; i++) {
            int chunk = tid + i * THREADS;
            int r = chunk >> 3;
            int c4 = (chunk & 7) << 2;
            float4 v = ra[i];
            if (sc) {
                float4 s = *reinterpret_cast<const float4*>(sc + k0 + c4);
                float4 t = *reinterpret_cast<const float4*>(sh + k0 + c4);
                v.x = fmaxf(v.x * s.x + t.x, 0.f);
                v.y = fmaxf(v.y * s.y + t.y, 0.f);
                v.z = fmaxf(v.z * s.z + t.z, 0.f);
                v.w = fmaxf(v.w * s.w + t.w, 0.f);
            }
            AS(buf, c4 + 0, r) = f2tf32(v.x);
            AS(buf, c4 + 1, r) = f2tf32(v.y);
            AS(buf, c4 + 2, r) = f2tf32(v.z);
            AS(buf, c4 + 3, r) = f2tf32(v.w);
        }
#pragma unroll
        for (int i = 0; i < BCH; i++) {
            int chunk = tid + i * THREADS;
            int r = chunk / BROWCH;
            int c4 = (chunk % BROWCH) * 4;
            uint4 u;
            u.x = f2tf32(rb[i].x); u.y = f2tf32(rb[i].y);
            u.z = f2tf32(rb[i].z); u.w = f2tf32(rb[i].w);
            *reinterpret_cast<uint4*>(&BS(buf, r, c4)) = u;
        }
    };

    load_stage(0);
    int buf = 0;
    for (int it = 0; it < total; ++it) {
        store_stage(it, buf);
        __syncthreads();
        if (it + 1 < total) load_stage(it + 1);

#pragma unroll
        for (int s = 0; s < BK / 8; ++s) {
            int kq = s * 8 + q;
            unsigned af[MT][4], bf[NT][2];
#pragma unroll
            for (int mt = 0; mt < MT; ++mt) {
                int m = wrow * WM + mt * 16 + g;
                af[mt][0] = AS(buf, kq, m);
                af[mt][1] = AS(buf, kq, m + 8);
                af[mt][2] = AS(buf, kq + 4, m);
                af[mt][3] = AS(buf, kq + 4, m + 8);
            }
#pragma unroll
            for (int nt = 0; nt < NT; ++nt) {
                int nn = wcol * WN + nt * 8 + g;
                bf[nt][0] = BS(buf, kq, nn);
                bf[nt][1] = BS(buf, kq + 4, nn);
            }
#pragma unroll
            for (int mt = 0; mt < MT; ++mt)
#pragma unroll
                for (int nt = 0; nt < NT; ++nt)
                    mma_tf32(acc[mt][nt], af[mt], bf[nt]);
        }
        buf ^= 1;
    }

#pragma unroll
    for (int mt = 0; mt < MT; ++mt) {
        int r0 = block_m + wrow * WM + mt * 16 + g;
        int r1 = r0 + 8;
#pragma unroll
        for (int nt = 0; nt < NT; ++nt) {
            int cn = block_n + wcol * WN + nt * 8 + q * 2;
            float b0 = 0.f, b1 = 0.f;
            if (bias) { b0 = __ldg(bias + cn); b1 = __ldg(bias + cn + 1); }
            if (r0 < M) {
                float2 t0 = make_float2(acc[mt][nt][0] + b0, acc[mt][nt][1] + b1);
                if (accumulate) {
                    float2 o = *reinterpret_cast<const float2*>(C + (size_t)r0 * N + cn);
                    t0.x += o.x; t0.y += o.y;
                }
                *reinterpret_cast<float2*>(C + (size_t)r0 * N + cn) = t0;
            }
            if (r1 < M) {
                float2 t1 = make_float2(acc[mt][nt][2] + b0, acc[mt][nt][3] + b1);
                if (accumulate) {
                    float2 o = *reinterpret_cast<const float2*>(C + (size_t)r1 * N + cn);
                    t1.x += o.x; t1.y += o.y;
                }
                *reinterpret_cast<float2*>(C + (size_t)r1 * N + cn) = t1;
            }
        }
    }
#undef AS
#undef BS
}

// ------------------------------- BatchNorm ----------------------------------
__global__ void colstats_partial(const float* __restrict__ H, int M,
                                 float* __restrict__ ps, float* __restrict__ pq) {
    int c = threadIdx.x;
    float s = 0.f, q = 0.f;
    for (int r = blockIdx.x; r < M; r += gridDim.x) {
        float v = H[(size_t)r * HIDDIM + c];
        s += v;
        q += v * v;
    }
    ps[blockIdx.x * HIDDIM + c] = s;
    pq[blockIdx.x * HIDDIM + c] = q;
}

__global__ void colstats_final(const float* __restrict__ ps, const float* __restrict__ pq,
                               int nb, float inv_m,
                               const float* __restrict__ g, const float* __restrict__ be,
                               float* __restrict__ scale, float* __restrict__ shift) {
    int c = threadIdx.x;
    float s = 0.f, q = 0.f;
    for (int b = 0; b < nb; b++) {
        s += ps[b * HIDDIM + c];
        q += pq[b * HIDDIM + c];
    }
    float mu  = s * inv_m;
    float var = q * inv_m - mu * mu;
    float rs  = rsqrtf(var + 1e-5f);
    float sc  = g[c] * rs;
    scale[c] = sc;
    shift[c] = be[c] - mu * sc;
}

// --------------------------------- launch -----------------------------------
extern "C" void kernel_launch(void* const* d_in, const int* in_sizes, int n_in,
                              void* d_out, int out_size) {
    const float* x   = (const float*)d_in[0];
    const int*   ei  = (const int*)d_in[1];
    const float* Wl0 = (const float*)d_in[2];
    const float* bl0 = (const float*)d_in[3];
    const float* Wr0 = (const float*)d_in[4];
    const float* Wl1 = (const float*)d_in[5];
    const float* bl1 = (const float*)d_in[6];
    const float* Wr1 = (const float*)d_in[7];
    const float* Wl2 = (const float*)d_in[8];
    const float* bl2 = (const float*)d_in[9];
    const float* Wr2 = (const float*)d_in[10];
    const float* g0  = (const float*)d_in[11];
    const float* be0 = (const float*)d_in[12];
    const float* g1  = (const float*)d_in[13];
    const float* be1 = (const float*)d_in[14];
    float* out = (float*)d_out;

    const int N  = NNODES;
    const int NE = NEDGES;

    float *agg, *h1, *h2, *y, *invdeg, *ps, *pq, *scale, *shift;
    __nv_bfloat16* h1b;
    int *cnt, *rowptr, *fill, *csr;
    cudaGetSymbolAddress((void**)&agg,    g_agg);
    cudaGetSymbolAddress((void**)&h1,     g_h1);
    cudaGetSymbolAddress((void**)&h2,     g_h2);
    cudaGetSymbolAddress((void**)&y,      g_y);
    cudaGetSymbolAddress((void**)&h1b,    g_h1b);
    cudaGetSymbolAddress((void**)&invdeg, g_invdeg);
    cudaGetSymbolAddress((void**)&cnt,    g_cnt);
    cudaGetSymbolAddress((void**)&rowptr, g_rowptr);
    cudaGetSymbolAddress((void**)&fill,   g_fill);
    cudaGetSymbolAddress((void**)&csr,    g_csr);
    cudaGetSymbolAddress((void**)&ps,     g_ps);
    cudaGetSymbolAddress((void**)&pq,     g_pq);
    cudaGetSymbolAddress((void**)&scale,  g_scale);
    cudaGetSymbolAddress((void**)&shift,  g_shift);

    const int SMEM_BIG   = (2 * 32 * (128 + 1) + 2 * 32 * (128 + 4)) * 4;  // 66816 B
    const int SMEM_SMALL = (2 * 32 * (128 + 1) + 2 * 32 * (64 + 4))  * 4;  // 50432 B
    static int smem_set = 0;
    if (!smem_set) {
        cudaFuncSetAttribute(gemm_tf32<128, 128, 64, 32>,
                             cudaFuncAttributeMaxDynamicSharedMemorySize, SMEM_BIG);
        cudaFuncSetAttribute(gemm_tf32<128, 64, 32, 32>,
                             cudaFuncAttributeMaxDynamicSharedMemorySize, SMEM_SMALL);
        smem_set = 1;
    }

    dim3 gridBig(HIDDIM / 128, (N + 127) / 128);
    dim3 gridSmall(OUTDIM / 64, (N + 127) / 128);
    const int AGG_BLOCKS = (N + 7) / 8;

    // ---- CSR build start (launch idx 0..2) ----
    zero_int_kernel<<<(N + 255) / 256, 256>>>(cnt, N);                       // idx 0
    hist_kernel<<<(NE + 255) / 256, 256>>>(ei, NE, cnt);                     // idx 1
    scan_prep_kernel<<<1, 1024>>>(cnt, rowptr, fill, invdeg, N);             // idx 2

    // ---- PROBE at idx 3 (ncu sample slot): x @ Wr0 + bl0 -> h1 ----
    // Single-pass K=128 GEMM, no CSR dependency. 6.55 GFLOP.
    gemm_tf32<128, 128, 64, 32><<<gridBig, 256, SMEM_BIG>>>(                 // idx 3
        x, Wr0, nullptr, nullptr,
        nullptr, nullptr, nullptr, nullptr,
        h1, N, HIDDIM, INDIM, bl0, 0);

    scatter_kernel<<<(NE + 255) / 256, 256>>>(ei, NE, fill, csr);            // idx 4

    // ---- Layer 0 rest: h1 += mean_agg(x) @ Wl0 ----
    agg_kernel<INDIM, false><<<AGG_BLOCKS, 256>>>(x, agg, rowptr, csr, invdeg, N);
    gemm_tf32<128, 128, 64, 32><<<gridBig, 256, SMEM_BIG>>>(
        agg, Wl0, nullptr, nullptr,
        nullptr, nullptr, nullptr, nullptr,
        h1, N, HIDDIM, INDIM, nullptr, 1);
    colstats_partial<<<NB_STATS, HIDDIM>>>(h1, N, ps, pq);
    colstats_final<<<1, HIDDIM>>>(ps, pq, NB_STATS, 1.0f / (float)N, g0, be0, scale, shift);

    // ---- Layer 1: h2 = mean_agg(act0(h1)) @ Wl1 + act0(h1) @ Wr1 + bl1 ----
    act_bf16_kernel<<<(N * HIDDIM / 4 + 255) / 256, 256>>>(
        (const float4*)h1, (__nv_bfloat162*)h1b, N * HIDDIM / 4, scale, shift);
    agg256_bf16_kernel<<<AGG_BLOCKS, 256>>>(h1b, agg, rowptr, csr, invdeg, N);
    gemm_tf32<128, 128, 64, 32><<<gridBig, 256, SMEM_BIG>>>(
        agg, Wl1, nullptr, nullptr,
        h1,  Wr1, scale, shift,
        h2, N, HIDDIM, HIDDIM, bl1, 0);
    colstats_partial<<<NB_STATS, HIDDIM>>>(h2, N, ps, pq);
    colstats_final<<<1, HIDDIM>>>(ps, pq, NB_STATS, 1.0f / (float)N, g1, be1, scale, shift);

    // ---- Layer 2: out = mean_agg(act1(h2) @ Wl2) + act1(h2) @ Wr2 + bl2 ----
    gemm_tf32<128, 64, 32, 32><<<gridSmall, 256, SMEM_SMALL>>>(
        h2, Wl2, scale, shift,
        nullptr, nullptr, nullptr, nullptr,
        y, N, OUTDIM, HIDDIM, nullptr, 0);
    gemm_tf32<128, 64, 32, 32><<<gridSmall, 256, SMEM_SMALL>>>(
        h2, Wr2, scale, shift,
        nullptr, nullptr, nullptr, nullptr,
        out, N, OUTDIM, HIDDIM, bl2, 0);
    agg_kernel<OUTDIM, true><<<AGG_BLOCKS, 256>>>(y, out, rowptr, csr, invdeg, N);
}

// round 9
// speedup vs baseline: 1.4053x; 1.4053x over previous
#include <cuda_runtime.h>
#include <cuda_bf16.h>
#include <cstdint>

// ---------------------------------------------------------------------------
// GraphSAGE (3x SAGEConv + BN/ReLU) on B200 / sm_100a.
//   - All GEMM inputs pre-rounded to tf32 (bit-exact relocation of the cvt.rna
//     that used to live inside the GEMM) -> GEMM does no conversion at all.
//   - GEMM v2: cp.async global->smem for A and B (no register staging, no
//     transpose), conflict-free fragment LDS (A [m][k] stride 36, B [k][n]
//     stride BN+8), __launch_bounds__(256,2) -> 2 CTAs/SM.
//   - Layer-1 aggregation gathers bf16 act0(h1); fp32 accumulate.
//   - Layer 2 trick: mean_agg(act(h2)) @ Wl2 == mean_agg(act(h2) @ Wl2).
// ---------------------------------------------------------------------------

#define NNODES 50000
#define NEDGES 1600000
#define INDIM  128
#define HIDDIM 256
#define OUTDIM 64
#define NB_STATS 512

// ------------------------- scratch (device globals) ------------------------
__device__ float g_agg[(size_t)NNODES * HIDDIM];
__device__ float g_h1 [(size_t)NNODES * HIDDIM];
__device__ float g_h2 [(size_t)NNODES * HIDDIM];
__device__ float g_y  [(size_t)NNODES * OUTDIM];
__device__ float g_xr [(size_t)NNODES * INDIM];          // tf32-rounded x
__device__ __align__(16) __nv_bfloat16 g_h1b[(size_t)NNODES * HIDDIM];
__device__ float g_wl0r[INDIM * HIDDIM];
__device__ float g_wr0r[INDIM * HIDDIM];
__device__ float g_wl1r[HIDDIM * HIDDIM];
__device__ float g_wr1r[HIDDIM * HIDDIM];
__device__ float g_wl2r[HIDDIM * OUTDIM];
__device__ float g_wr2r[HIDDIM * OUTDIM];
__device__ float g_invdeg[NNODES];
__device__ int   g_cnt[NNODES];
__device__ int   g_rowptr[NNODES + 1];
__device__ int   g_fill[NNODES];
__device__ int   g_csr[NEDGES];
__device__ float g_ps[NB_STATS * HIDDIM];
__device__ float g_pq[NB_STATS * HIDDIM];
__device__ __align__(16) float g_scale[HIDDIM];
__device__ __align__(16) float g_shift[HIDDIM];

// --------------------------- tf32 / cp.async utils --------------------------
__device__ __forceinline__ unsigned f2tf32(float f) {
    unsigned u;
    asm("cvt.rna.tf32.f32 %0, %1;" : "=r"(u) : "f"(f));
    return u;
}
__device__ __forceinline__ float f2tf32f(float f) { return __uint_as_float(f2tf32(f)); }

__device__ __forceinline__ void cp_async16(uint32_t saddr, const void* gptr, bool pred) {
    int sz = pred ? 16 : 0;
    asm volatile("cp.async.cg.shared.global [%0], [%1], 16, %2;\n"
                 :: "r"(saddr), "l"(gptr), "r"(sz));
}
__device__ __forceinline__ void cp_commit() {
    asm volatile("cp.async.commit_group;\n" ::: "memory");
}
__device__ __forceinline__ void cp_wait0() {
    asm volatile("cp.async.wait_group 0;\n" ::: "memory");
}

// ------------------------------- CSR build ---------------------------------
__global__ void zero_int_kernel(int* p, int n) {
    int i = blockIdx.x * blockDim.x + threadIdx.x;
    if (i < n) p[i] = 0;
}

__global__ void hist_kernel(const int* __restrict__ ei, int ne, int* __restrict__ cnt) {
    int e = blockIdx.x * blockDim.x + threadIdx.x;
    if (e < ne) {
        int d = ei[ne + e];
        if ((unsigned)d < (unsigned)NNODES)
            atomicAdd(&cnt[d], 1);
    }
}

__global__ void scan_prep_kernel(const int* __restrict__ cnt, int* __restrict__ rowptr,
                                 int* __restrict__ fill, float* __restrict__ invdeg, int n) {
    __shared__ int wsum[32];
    __shared__ int carry_s;
    int tid = threadIdx.x, lane = tid & 31, wid = tid >> 5;
    if (tid == 0) { carry_s = 0; rowptr[0] = 0; }
    __syncthreads();
    for (int base = 0; base < n; base += 1024) {
        int i = base + tid;
        int v = (i < n) ? cnt[i] : 0;
        int s = v;
#pragma unroll
        for (int off = 1; off < 32; off <<= 1) {
            int t = __shfl_up_sync(0xffffffffu, s, off);
            if (lane >= off) s += t;
        }
        if (lane == 31) wsum[wid] = s;
        __syncthreads();
        if (wid == 0) {
            int w = wsum[lane];
#pragma unroll
            for (int off = 1; off < 32; off <<= 1) {
                int t = __shfl_up_sync(0xffffffffu, w, off);
                if (lane >= off) w += t;
            }
            wsum[lane] = w;
        }
        __syncthreads();
        int incl = s + (wid ? wsum[wid - 1] : 0) + carry_s;
        if (i < n) {
            rowptr[i + 1] = incl;
            fill[i] = incl - v;
            invdeg[i] = 1.0f / (float)(v > 0 ? v : 1);
        }
        __syncthreads();
        if (tid == 1023) carry_s = incl;
        __syncthreads();
    }
}

__global__ void scatter_kernel(const int* __restrict__ ei, int ne,
                               int* __restrict__ fill, int* __restrict__ csr) {
    int e = blockIdx.x * blockDim.x + threadIdx.x;
    if (e < ne) {
        int s = ei[e];
        int d = ei[ne + e];
        if ((unsigned)d < (unsigned)NNODES && (unsigned)s < (unsigned)NNODES) {
            int pos = atomicAdd(&fill[d], 1);
            if ((unsigned)pos < (unsigned)NEDGES)
                csr[pos] = s;
        }
    }
}

// ----------------------------- pre-round kernel -----------------------------
__global__ void round_tf32_kernel(const float4* __restrict__ src, float4* __restrict__ dst, int n4) {
    int i = blockIdx.x * blockDim.x + threadIdx.x;
    if (i >= n4) return;
    float4 v = src[i];
    v.x = f2tf32f(v.x); v.y = f2tf32f(v.y); v.z = f2tf32f(v.z); v.w = f2tf32f(v.w);
    dst[i] = v;
}

// ---------------- act (BN+ReLU) in-place + round, optional bf16 -------------
__global__ void act_round_kernel(float4* __restrict__ H, __nv_bfloat162* __restrict__ O2,
                                 int n4, const float* __restrict__ sc, const float* __restrict__ sh) {
    int i = blockIdx.x * blockDim.x + threadIdx.x;
    if (i >= n4) return;
    int c = (i * 4) & (HIDDIM - 1);
    float4 v = H[i];
    v.x = fmaxf(v.x * __ldg(sc + c + 0) + __ldg(sh + c + 0), 0.f);
    v.y = fmaxf(v.y * __ldg(sc + c + 1) + __ldg(sh + c + 1), 0.f);
    v.z = fmaxf(v.z * __ldg(sc + c + 2) + __ldg(sh + c + 2), 0.f);
    v.w = fmaxf(v.w * __ldg(sc + c + 3) + __ldg(sh + c + 3), 0.f);
    if (O2) {
        O2[i * 2 + 0] = __floats2bfloat162_rn(v.x, v.y);
        O2[i * 2 + 1] = __floats2bfloat162_rn(v.z, v.w);
    }
    float4 r;
    r.x = f2tf32f(v.x); r.y = f2tf32f(v.y); r.z = f2tf32f(v.z); r.w = f2tf32f(v.w);
    H[i] = r;
}

// ------------------------- bf16 aggregation (D=256) -------------------------
// Output rounded to tf32 (feeds GEMM A directly).
__global__ void agg256_bf16_kernel(const __nv_bfloat16* __restrict__ Xb, float* __restrict__ Out,
                                   const int* __restrict__ rowptr, const int* __restrict__ csr,
                                   const float* __restrict__ invdeg, int n_nodes) {
    int node = (blockIdx.x * blockDim.x + threadIdx.x) >> 5;
    if (node >= n_nodes) return;
    int lane = threadIdx.x & 31;
    int doff = lane * 8;

    float acc0[8], acc1[8];
#pragma unroll
    for (int i = 0; i < 8; i++) { acc0[i] = 0.f; acc1[i] = 0.f; }

    int beg = rowptr[node];
    int end = rowptr[node + 1];
    int e = beg;

    auto accum = [&](uint4 u, float* acc) {
        __nv_bfloat162 b0 = *reinterpret_cast<__nv_bfloat162*>(&u.x);
        __nv_bfloat162 b1 = *reinterpret_cast<__nv_bfloat162*>(&u.y);
        __nv_bfloat162 b2 = *reinterpret_cast<__nv_bfloat162*>(&u.z);
        __nv_bfloat162 b3 = *reinterpret_cast<__nv_bfloat162*>(&u.w);
        float2 f0 = __bfloat1622float2(b0);
        float2 f1 = __bfloat1622float2(b1);
        float2 f2 = __bfloat1622float2(b2);
        float2 f3 = __bfloat1622float2(b3);
        acc[0] += f0.x; acc[1] += f0.y;
        acc[2] += f1.x; acc[3] += f1.y;
        acc[4] += f2.x; acc[5] += f2.y;
        acc[6] += f3.x; acc[7] += f3.y;
    };

    for (; e + 3 < end; e += 4) {
        int s0 = __ldg(csr + e);
        int s1 = __ldg(csr + e + 1);
        int s2 = __ldg(csr + e + 2);
        int s3 = __ldg(csr + e + 3);
        uint4 u0 = __ldg(reinterpret_cast<const uint4*>(Xb + (size_t)s0 * HIDDIM + doff));
        uint4 u1 = __ldg(reinterpret_cast<const uint4*>(Xb + (size_t)s1 * HIDDIM + doff));
        uint4 u2 = __ldg(reinterpret_cast<const uint4*>(Xb + (size_t)s2 * HIDDIM + doff));
        uint4 u3 = __ldg(reinterpret_cast<const uint4*>(Xb + (size_t)s3 * HIDDIM + doff));
        accum(u0, acc0); accum(u1, acc1); accum(u2, acc0); accum(u3, acc1);
    }
    for (; e < end; e++) {
        int s0 = __ldg(csr + e);
        uint4 u0 = __ldg(reinterpret_cast<const uint4*>(Xb + (size_t)s0 * HIDDIM + doff));
        accum(u0, acc0);
    }

    float w = __ldg(invdeg + node);
    float* o = Out + (size_t)node * HIDDIM + doff;
    float4 o0, o1;
    o0.x = f2tf32f((acc0[0] + acc1[0]) * w);
    o0.y = f2tf32f((acc0[1] + acc1[1]) * w);
    o0.z = f2tf32f((acc0[2] + acc1[2]) * w);
    o0.w = f2tf32f((acc0[3] + acc1[3]) * w);
    o1.x = f2tf32f((acc0[4] + acc1[4]) * w);
    o1.y = f2tf32f((acc0[5] + acc1[5]) * w);
    o1.z = f2tf32f((acc0[6] + acc1[6]) * w);
    o1.w = f2tf32f((acc0[7] + acc1[7]) * w);
    *reinterpret_cast<float4*>(o)     = o0;
    *reinterpret_cast<float4*>(o + 4) = o1;
}

// ------------------------ fp32 aggregation (D=64/128) -----------------------
// ROUND: round output to tf32 (when it feeds a GEMM A operand).
template <int D, bool ADD, bool ROUND>
__global__ void agg_kernel(const float* __restrict__ X, float* __restrict__ Out,
                           const int* __restrict__ rowptr, const int* __restrict__ csr,
                           const float* __restrict__ invdeg, int n_nodes) {
    constexpr int PL = D / 32;
    int node = (blockIdx.x * blockDim.x + threadIdx.x) >> 5;
    if (node >= n_nodes) return;
    int lane = threadIdx.x & 31;
    int doff = lane * PL;

    float acc0[PL], acc1[PL];
#pragma unroll
    for (int i = 0; i < PL; i++) { acc0[i] = 0.f; acc1[i] = 0.f; }

    int beg = rowptr[node];
    int end = rowptr[node + 1];
    int e = beg;

    if constexpr (PL == 4) {
        for (; e + 3 < end; e += 4) {
            int s0 = __ldg(csr + e);
            int s1 = __ldg(csr + e + 1);
            int s2 = __ldg(csr + e + 2);
            int s3 = __ldg(csr + e + 3);
            float4 v0 = __ldg(reinterpret_cast<const float4*>(X + (size_t)s0 * D + doff));
            float4 v1 = __ldg(reinterpret_cast<const float4*>(X + (size_t)s1 * D + doff));
            float4 v2 = __ldg(reinterpret_cast<const float4*>(X + (size_t)s2 * D + doff));
            float4 v3 = __ldg(reinterpret_cast<const float4*>(X + (size_t)s3 * D + doff));
            acc0[0] += v0.x + v2.x;  acc1[0] += v1.x + v3.x;
            acc0[1] += v0.y + v2.y;  acc1[1] += v1.y + v3.y;
            acc0[2] += v0.z + v2.z;  acc1[2] += v1.z + v3.z;
            acc0[3] += v0.w + v2.w;  acc1[3] += v1.w + v3.w;
        }
        for (; e < end; e++) {
            int s0 = __ldg(csr + e);
            float4 v0 = __ldg(reinterpret_cast<const float4*>(X + (size_t)s0 * D + doff));
            acc0[0] += v0.x; acc0[1] += v0.y; acc0[2] += v0.z; acc0[3] += v0.w;
        }
    } else {
        for (; e + 3 < end; e += 4) {
            int s0 = __ldg(csr + e);
            int s1 = __ldg(csr + e + 1);
            int s2 = __ldg(csr + e + 2);
            int s3 = __ldg(csr + e + 3);
            float2 v0 = __ldg(reinterpret_cast<const float2*>(X + (size_t)s0 * D + doff));
            float2 v1 = __ldg(reinterpret_cast<const float2*>(X + (size_t)s1 * D + doff));
            float2 v2 = __ldg(reinterpret_cast<const float2*>(X + (size_t)s2 * D + doff));
            float2 v3 = __ldg(reinterpret_cast<const float2*>(X + (size_t)s3 * D + doff));
            acc0[0] += v0.x + v2.x;  acc1[0] += v1.x + v3.x;
            acc0[1] += v0.y + v2.y;  acc1[1] += v1.y + v3.y;
        }
        for (; e < end; e++) {
            int s0 = __ldg(csr + e);
            float2 v0 = __ldg(reinterpret_cast<const float2*>(X + (size_t)s0 * D + doff));
            acc0[0] += v0.x; acc0[1] += v0.y;
        }
    }

    float w = __ldg(invdeg + node);
    float* o = Out + (size_t)node * D + doff;
#pragma unroll
    for (int i = 0; i < PL; i++) {
        float a = (acc0[i] + acc1[i]) * w;
        if constexpr (ROUND) a = f2tf32f(a);
        if constexpr (ADD) o[i] += a;
        else               o[i]  = a;
    }
}

// ------------------------------ TF32 GEMM v2 ---------------------------------
__device__ __forceinline__ void mma_tf32(float c[4], const unsigned a[4], const unsigned b[2]) {
    asm volatile(
        "mma.sync.aligned.m16n8k8.row.col.f32.tf32.tf32.f32 "
        "{%0,%1,%2,%3}, {%4,%5,%6,%7}, {%8,%9}, {%0,%1,%2,%3};"
        : "+f"(c[0]), "+f"(c[1]), "+f"(c[2]), "+f"(c[3])
        : "r"(a[0]), "r"(a[1]), "r"(a[2]), "r"(a[3]), "r"(b[0]), "r"(b[1]));
}

// C = A0@B0 (+ A1@B1) (+ bias). All inputs PRE-ROUNDED tf32-in-fp32.
// A [m][k] smem stride 36, B [k][n] smem stride BN+8: conflict-free frag LDS.
// cp.async double-buffered, 1 sync per K-tile, 2 CTAs/SM.
template <int BM, int BN, int WM, int WN>
__global__ void __launch_bounds__(256, 2)
gemm_tf32(const float* __restrict__ A0, const float* __restrict__ B0g,
          const float* __restrict__ A1, const float* __restrict__ B1g,
          float* __restrict__ C, int M, int N, int K,
          const float* __restrict__ bias) {
    constexpr int BK = 32, THREADS = 256;
    constexpr int WCOLS = BN / WN;
    constexpr int MT = WM / 16, NT = WN / 8;
    constexpr int AST = BK + 4;                 // 36
    constexpr int BST = BN + 8;                 // 136 / 72
    constexpr int ACH = (BM * BK) / (4 * THREADS);
    constexpr int BCH = (BK * BN) / (4 * THREADS);
    constexpr int BROWCH = BN / 4;
    constexpr int ABUF = BM * AST;
    constexpr int BBUF = BK * BST;
    static_assert((BM / WM) * (BN / WN) == 8, "8 warps");

    extern __shared__ float smem_f[];
    float* Asm = smem_f;                        // [2][BM][AST]
    float* Bsm = smem_f + 2 * ABUF;             // [2][BK][BST]

    int tid = threadIdx.x, lane = tid & 31, warp = tid >> 5;
    int wrow = warp / WCOLS, wcol = warp % WCOLS;
    int block_m = blockIdx.y * BM, block_n = blockIdx.x * BN;
    int g = lane >> 2, q = lane & 3;

    uint32_t AsmAddr = (uint32_t)__cvta_generic_to_shared(Asm);
    uint32_t BsmAddr = (uint32_t)__cvta_generic_to_shared(Bsm);

    float acc[MT][NT][4];
#pragma unroll
    for (int mt = 0; mt < MT; mt++)
#pragma unroll
        for (int nt = 0; nt < NT; nt++)
#pragma unroll
            for (int r = 0; r < 4; r++) acc[mt][nt][r] = 0.0f;

    const int kiters = K / BK;
    const int npass = A1 ? 2 : 1;
    const int total = npass * kiters;

    auto issue_stage = [&](int it, int buf) {
        int pass = it / kiters;
        int k0 = (it - pass * kiters) * BK;
        const float* Ap = pass ? A1 : A0;
        const float* Bp = pass ? B1g : B0g;
#pragma unroll
        for (int i = 0; i < ACH; i++) {
            int chunk = tid + i * THREADS;
            int r = chunk >> 3;                 // row in tile (8 chunks/row)
            int c4 = (chunk & 7) << 2;          // col (float units)
            int gr = block_m + r;
            uint32_t dst = AsmAddr + (buf * ABUF + r * AST + c4) * 4;
            cp_async16(dst, Ap + (size_t)gr * K + k0 + c4, gr < M);
        }
#pragma unroll
        for (int i = 0; i < BCH; i++) {
            int chunk = tid + i * THREADS;
            int r = chunk / BROWCH;
            int c4 = (chunk % BROWCH) * 4;
            uint32_t dst = BsmAddr + (buf * BBUF + r * BST + c4) * 4;
            cp_async16(dst, Bp + (size_t)(k0 + r) * N + block_n + c4, true);
        }
        cp_commit();
    };

    issue_stage(0, 0);
    int buf = 0;
    for (int it = 0; it < total; ++it) {
        cp_wait0();
        __syncthreads();
        if (it + 1 < total) issue_stage(it + 1, buf ^ 1);

        const float* Ab = Asm + buf * ABUF;
        const float* Bb = Bsm + buf * BBUF;
#pragma unroll
        for (int s = 0; s < BK / 8; ++s) {
            int kq = s * 8 + q;
            unsigned af[MT][4], bf[NT][2];
#pragma unroll
            for (int mt = 0; mt < MT; ++mt) {
                int m = wrow * WM + mt * 16 + g;
                af[mt][0] = __float_as_uint(Ab[m * AST + kq]);
                af[mt][1] = __float_as_uint(Ab[(m + 8) * AST + kq]);
                af[mt][2] = __float_as_uint(Ab[m * AST + kq + 4]);
                af[mt][3] = __float_as_uint(Ab[(m + 8) * AST + kq + 4]);
            }
#pragma unroll
            for (int nt = 0; nt < NT; ++nt) {
                int nn = wcol * WN + nt * 8 + g;
                bf[nt][0] = __float_as_uint(Bb[kq * BST + nn]);
                bf[nt][1] = __float_as_uint(Bb[(kq + 4) * BST + nn]);
            }
#pragma unroll
            for (int mt = 0; mt < MT; ++mt)
#pragma unroll
                for (int nt = 0; nt < NT; ++nt)
                    mma_tf32(acc[mt][nt], af[mt], bf[nt]);
        }
        buf ^= 1;
    }

#pragma unroll
    for (int mt = 0; mt < MT; ++mt) {
        int r0 = block_m + wrow * WM + mt * 16 + g;
        int r1 = r0 + 8;
#pragma unroll
        for (int nt = 0; nt < NT; ++nt) {
            int cn = block_n + wcol * WN + nt * 8 + q * 2;
            float b0 = 0.f, b1 = 0.f;
            if (bias) { b0 = __ldg(bias + cn); b1 = __ldg(bias + cn + 1); }
            if (r0 < M) {
                float2 t0 = make_float2(acc[mt][nt][0] + b0, acc[mt][nt][1] + b1);
                *reinterpret_cast<float2*>(C + (size_t)r0 * N + cn) = t0;
            }
            if (r1 < M) {
                float2 t1 = make_float2(acc[mt][nt][2] + b0, acc[mt][nt][3] + b1);
                *reinterpret_cast<float2*>(C + (size_t)r1 * N + cn) = t1;
            }
        }
    }
}

// ------------------------------- BatchNorm ----------------------------------
__global__ void colstats_partial(const float* __restrict__ H, int M,
                                 float* __restrict__ ps, float* __restrict__ pq) {
    int c = threadIdx.x;
    float s = 0.f, q = 0.f;
    for (int r = blockIdx.x; r < M; r += gridDim.x) {
        float v = H[(size_t)r * HIDDIM + c];
        s += v;
        q += v * v;
    }
    ps[blockIdx.x * HIDDIM + c] = s;
    pq[blockIdx.x * HIDDIM + c] = q;
}

__global__ void colstats_final(const float* __restrict__ ps, const float* __restrict__ pq,
                               int nb, float inv_m,
                               const float* __restrict__ g, const float* __restrict__ be,
                               float* __restrict__ scale, float* __restrict__ shift) {
    int c = threadIdx.x;
    float s = 0.f, q = 0.f;
    for (int b = 0; b < nb; b++) {
        s += ps[b * HIDDIM + c];
        q += pq[b * HIDDIM + c];
    }
    float mu  = s * inv_m;
    float var = q * inv_m - mu * mu;
    float rs  = rsqrtf(var + 1e-5f);
    float sc  = g[c] * rs;
    scale[c] = sc;
    shift[c] = be[c] - mu * sc;
}

// --------------------------------- launch -----------------------------------
extern "C" void kernel_launch(void* const* d_in, const int* in_sizes, int n_in,
                              void* d_out, int out_size) {
    const float* x   = (const float*)d_in[0];
    const int*   ei  = (const int*)d_in[1];
    const float* Wl0 = (const float*)d_in[2];
    const float* bl0 = (const float*)d_in[3];
    const float* Wr0 = (const float*)d_in[4];
    const float* Wl1 = (const float*)d_in[5];
    const float* bl1 = (const float*)d_in[6];
    const float* Wr1 = (const float*)d_in[7];
    const float* Wl2 = (const float*)d_in[8];
    const float* bl2 = (const float*)d_in[9];
    const float* Wr2 = (const float*)d_in[10];
    const float* g0  = (const float*)d_in[11];
    const float* be0 = (const float*)d_in[12];
    const float* g1  = (const float*)d_in[13];
    const float* be1 = (const float*)d_in[14];
    float* out = (float*)d_out;

    const int N  = NNODES;
    const int NE = NEDGES;

    float *agg, *h1, *h2, *y, *xr, *invdeg, *ps, *pq, *scale, *shift;
    float *wl0r, *wr0r, *wl1r, *wr1r, *wl2r, *wr2r;
    __nv_bfloat16* h1b;
    int *cnt, *rowptr, *fill, *csr;
    cudaGetSymbolAddress((void**)&agg,    g_agg);
    cudaGetSymbolAddress((void**)&h1,     g_h1);
    cudaGetSymbolAddress((void**)&h2,     g_h2);
    cudaGetSymbolAddress((void**)&y,      g_y);
    cudaGetSymbolAddress((void**)&xr,     g_xr);
    cudaGetSymbolAddress((void**)&h1b,    g_h1b);
    cudaGetSymbolAddress((void**)&wl0r,   g_wl0r);
    cudaGetSymbolAddress((void**)&wr0r,   g_wr0r);
    cudaGetSymbolAddress((void**)&wl1r,   g_wl1r);
    cudaGetSymbolAddress((void**)&wr1r,   g_wr1r);
    cudaGetSymbolAddress((void**)&wl2r,   g_wl2r);
    cudaGetSymbolAddress((void**)&wr2r,   g_wr2r);
    cudaGetSymbolAddress((void**)&invdeg, g_invdeg);
    cudaGetSymbolAddress((void**)&cnt,    g_cnt);
    cudaGetSymbolAddress((void**)&rowptr, g_rowptr);
    cudaGetSymbolAddress((void**)&fill,   g_fill);
    cudaGetSymbolAddress((void**)&csr,    g_csr);
    cudaGetSymbolAddress((void**)&ps,     g_ps);
    cudaGetSymbolAddress((void**)&pq,     g_pq);
    cudaGetSymbolAddress((void**)&scale,  g_scale);
    cudaGetSymbolAddress((void**)&shift,  g_shift);

    // smem: As 2*128*36 + Bs 2*32*(BN+8) floats
    const int SMEM_BIG   = (2 * 128 * 36 + 2 * 32 * 136) * 4;  // 71680 B
    const int SMEM_SMALL = (2 * 128 * 36 + 2 * 32 * 72)  * 4;  // 55296 B
    static int smem_set = 0;
    if (!smem_set) {
        cudaFuncSetAttribute(gemm_tf32<128, 128, 64, 32>,
                             cudaFuncAttributeMaxDynamicSharedMemorySize, SMEM_BIG);
        cudaFuncSetAttribute(gemm_tf32<128, 64, 32, 32>,
                             cudaFuncAttributeMaxDynamicSharedMemorySize, SMEM_SMALL);
        smem_set = 1;
    }

    dim3 gridBig(HIDDIM / 128, (N + 127) / 128);
    dim3 gridSmall(OUTDIM / 64, (N + 127) / 128);
    const int AGG_BLOCKS = (N + 7) / 8;

    // ---- CSR build + pre-rounding (independent; interleaved) ----
    zero_int_kernel<<<(N + 255) / 256, 256>>>(cnt, N);
    hist_kernel<<<(NE + 255) / 256, 256>>>(ei, NE, cnt);
    scan_prep_kernel<<<1, 1024>>>(cnt, rowptr, fill, invdeg, N);
    scatter_kernel<<<(NE + 255) / 256, 256>>>(ei, NE, fill, csr);
    round_tf32_kernel<<<(N * INDIM / 4 + 255) / 256, 256>>>((const float4*)x, (float4*)xr, N * INDIM / 4);
    round_tf32_kernel<<<(INDIM * HIDDIM / 4 + 255) / 256, 256>>>((const float4*)Wl0, (float4*)wl0r, INDIM * HIDDIM / 4);
    round_tf32_kernel<<<(INDIM * HIDDIM / 4 + 255) / 256, 256>>>((const float4*)Wr0, (float4*)wr0r, INDIM * HIDDIM / 4);
    round_tf32_kernel<<<(HIDDIM * HIDDIM / 4 + 255) / 256, 256>>>((const float4*)Wl1, (float4*)wl1r, HIDDIM * HIDDIM / 4);
    round_tf32_kernel<<<(HIDDIM * HIDDIM / 4 + 255) / 256, 256>>>((const float4*)Wr1, (float4*)wr1r, HIDDIM * HIDDIM / 4);
    round_tf32_kernel<<<(HIDDIM * OUTDIM / 4 + 255) / 256, 256>>>((const float4*)Wl2, (float4*)wl2r, HIDDIM * OUTDIM / 4);
    round_tf32_kernel<<<(HIDDIM * OUTDIM / 4 + 255) / 256, 256>>>((const float4*)Wr2, (float4*)wr2r, HIDDIM * OUTDIM / 4);

    // ---- Layer 0: h1 = mean_agg(x) @ Wl0 + x @ Wr0 + bl0 ----
    agg_kernel<INDIM, false, true><<<AGG_BLOCKS, 256>>>(x, agg, rowptr, csr, invdeg, N);
    gemm_tf32<128, 128, 64, 32><<<gridBig, 256, SMEM_BIG>>>(
        agg, wl0r, xr, wr0r, h1, N, HIDDIM, INDIM, bl0);
    colstats_partial<<<NB_STATS, HIDDIM>>>(h1, N, ps, pq);
    colstats_final<<<1, HIDDIM>>>(ps, pq, NB_STATS, 1.0f / (float)N, g0, be0, scale, shift);

    // ---- Layer 1: h2 = mean_agg(act0(h1)) @ Wl1 + act0(h1) @ Wr1 + bl1 ----
    // act in-place on h1 (tf32-rounded) + bf16 copy for the gather.
    act_round_kernel<<<(N * HIDDIM / 4 + 255) / 256, 256>>>(
        (float4*)h1, (__nv_bfloat162*)h1b, N * HIDDIM / 4, scale, shift);
    agg256_bf16_kernel<<<AGG_BLOCKS, 256>>>(h1b, agg, rowptr, csr, invdeg, N);
    gemm_tf32<128, 128, 64, 32><<<gridBig, 256, SMEM_BIG>>>(
        agg, wl1r, h1, wr1r, h2, N, HIDDIM, HIDDIM, bl1);
    colstats_partial<<<NB_STATS, HIDDIM>>>(h2, N, ps, pq);
    colstats_final<<<1, HIDDIM>>>(ps, pq, NB_STATS, 1.0f / (float)N, g1, be1, scale, shift);

    // ---- Layer 2: out = mean_agg(act1(h2) @ Wl2) + act1(h2) @ Wr2 + bl2 ----
    act_round_kernel<<<(N * HIDDIM / 4 + 255) / 256, 256>>>(
        (float4*)h2, nullptr, N * HIDDIM / 4, scale, shift);
    gemm_tf32<128, 64, 32, 32><<<gridSmall, 256, SMEM_SMALL>>>(
        h2, wl2r, nullptr, nullptr, y, N, OUTDIM, HIDDIM, nullptr);
    gemm_tf32<128, 64, 32, 32><<<gridSmall, 256, SMEM_SMALL>>>(
        h2, wr2r, nullptr, nullptr, out, N, OUTDIM, HIDDIM, bl2);
    agg_kernel<OUTDIM, true, false><<<AGG_BLOCKS, 256>>>(y, out, rowptr, csr, invdeg, N);
}

// round 10
// speedup vs baseline: 1.4637x; 1.0415x over previous
#include <cuda_runtime.h>
#include <cuda_bf16.h>
#include <cuda_fp16.h>
#include <cstdint>

// ---------------------------------------------------------------------------
// GraphSAGE (3x SAGEConv + BN/ReLU) on B200 / sm_100a.
//   - All GEMM inputs pre-rounded to tf32; GEMM v2 does raw cp.async loads,
//     conflict-free fragment LDS, 2 CTAs/SM.
//   - Layer-0 gather: fp16 copy of x (same 10-bit mantissa as tf32).
//   - Layer-1 gather: bf16 copy of act0(h1).
//   - Layer-2: ONE fused N=128 GEMM over [Wl2|Wr2]; epilogue writes y as fp16
//     (cols 0-63) and out+bl2 (cols 64-127). agg64 gathers fp16 y.
// ---------------------------------------------------------------------------

#define NNODES 50000
#define NEDGES 1600000
#define INDIM  128
#define HIDDIM 256
#define OUTDIM 64
#define NB_STATS 512

// ------------------------- scratch (device globals) ------------------------
__device__ float g_agg[(size_t)NNODES * HIDDIM];
__device__ float g_h1 [(size_t)NNODES * HIDDIM];
__device__ float g_h2 [(size_t)NNODES * HIDDIM];
__device__ float g_xr [(size_t)NNODES * INDIM];                 // tf32 x
__device__ __align__(16) __half g_xh[(size_t)NNODES * INDIM];   // fp16 x
__device__ __align__(16) __half g_yh[(size_t)NNODES * OUTDIM];  // fp16 y
__device__ __align__(16) __nv_bfloat16 g_h1b[(size_t)NNODES * HIDDIM];
__device__ float g_wl0r[INDIM * HIDDIM];
__device__ float g_wr0r[INDIM * HIDDIM];
__device__ float g_wl1r[HIDDIM * HIDDIM];
__device__ float g_wr1r[HIDDIM * HIDDIM];
__device__ float g_wcat[HIDDIM * 128];                          // [Wl2|Wr2] tf32
__device__ float g_invdeg[NNODES];
__device__ int   g_cnt[NNODES];
__device__ int   g_rowptr[NNODES + 1];
__device__ int   g_fill[NNODES];
__device__ int   g_csr[NEDGES];
__device__ float g_ps[NB_STATS * HIDDIM];
__device__ float g_pq[NB_STATS * HIDDIM];
__device__ __align__(16) float g_scale[HIDDIM];
__device__ __align__(16) float g_shift[HIDDIM];

// --------------------------- tf32 / cp.async utils --------------------------
__device__ __forceinline__ unsigned f2tf32(float f) {
    unsigned u;
    asm("cvt.rna.tf32.f32 %0, %1;" : "=r"(u) : "f"(f));
    return u;
}
__device__ __forceinline__ float f2tf32f(float f) { return __uint_as_float(f2tf32(f)); }

__device__ __forceinline__ void cp_async16(uint32_t saddr, const void* gptr, bool pred) {
    int sz = pred ? 16 : 0;
    asm volatile("cp.async.cg.shared.global [%0], [%1], 16, %2;\n"
                 :: "r"(saddr), "l"(gptr), "r"(sz));
}
__device__ __forceinline__ void cp_commit() {
    asm volatile("cp.async.commit_group;\n" ::: "memory");
}
__device__ __forceinline__ void cp_wait0() {
    asm volatile("cp.async.wait_group 0;\n" ::: "memory");
}

// ------------------------------- CSR build ---------------------------------
__global__ void zero_int_kernel(int* p, int n) {
    int i = blockIdx.x * blockDim.x + threadIdx.x;
    if (i < n) p[i] = 0;
}

__global__ void hist_kernel(const int* __restrict__ ei, int ne, int* __restrict__ cnt) {
    int e = blockIdx.x * blockDim.x + threadIdx.x;
    if (e < ne) {
        int d = ei[ne + e];
        if ((unsigned)d < (unsigned)NNODES)
            atomicAdd(&cnt[d], 1);
    }
}

__global__ void scan_prep_kernel(const int* __restrict__ cnt, int* __restrict__ rowptr,
                                 int* __restrict__ fill, float* __restrict__ invdeg, int n) {
    __shared__ int wsum[32];
    __shared__ int carry_s;
    int tid = threadIdx.x, lane = tid & 31, wid = tid >> 5;
    if (tid == 0) { carry_s = 0; rowptr[0] = 0; }
    __syncthreads();
    for (int base = 0; base < n; base += 1024) {
        int i = base + tid;
        int v = (i < n) ? cnt[i] : 0;
        int s = v;
#pragma unroll
        for (int off = 1; off < 32; off <<= 1) {
            int t = __shfl_up_sync(0xffffffffu, s, off);
            if (lane >= off) s += t;
        }
        if (lane == 31) wsum[wid] = s;
        __syncthreads();
        if (wid == 0) {
            int w = wsum[lane];
#pragma unroll
            for (int off = 1; off < 32; off <<= 1) {
                int t = __shfl_up_sync(0xffffffffu, w, off);
                if (lane >= off) w += t;
            }
            wsum[lane] = w;
        }
        __syncthreads();
        int incl = s + (wid ? wsum[wid - 1] : 0) + carry_s;
        if (i < n) {
            rowptr[i + 1] = incl;
            fill[i] = incl - v;
            invdeg[i] = 1.0f / (float)(v > 0 ? v : 1);
        }
        __syncthreads();
        if (tid == 1023) carry_s = incl;
        __syncthreads();
    }
}

__global__ void scatter_kernel(const int* __restrict__ ei, int ne,
                               int* __restrict__ fill, int* __restrict__ csr) {
    int e = blockIdx.x * blockDim.x + threadIdx.x;
    if (e < ne) {
        int s = ei[e];
        int d = ei[ne + e];
        if ((unsigned)d < (unsigned)NNODES && (unsigned)s < (unsigned)NNODES) {
            int pos = atomicAdd(&fill[d], 1);
            if ((unsigned)pos < (unsigned)NEDGES)
                csr[pos] = s;
        }
    }
}

// ----------------------------- prologue kernels ------------------------------
__global__ void round_tf32_kernel(const float4* __restrict__ src, float4* __restrict__ dst, int n4) {
    int i = blockIdx.x * blockDim.x + threadIdx.x;
    if (i >= n4) return;
    float4 v = src[i];
    v.x = f2tf32f(v.x); v.y = f2tf32f(v.y); v.z = f2tf32f(v.z); v.w = f2tf32f(v.w);
    dst[i] = v;
}

// x -> xr (tf32) and xh (fp16)
__global__ void round_x_kernel(const float4* __restrict__ src, float4* __restrict__ dst,
                               __half2* __restrict__ dh2, int n4) {
    int i = blockIdx.x * blockDim.x + threadIdx.x;
    if (i >= n4) return;
    float4 v = src[i];
    dh2[i * 2 + 0] = __floats2half2_rn(v.x, v.y);
    dh2[i * 2 + 1] = __floats2half2_rn(v.z, v.w);
    v.x = f2tf32f(v.x); v.y = f2tf32f(v.y); v.z = f2tf32f(v.z); v.w = f2tf32f(v.w);
    dst[i] = v;
}

// wcat[k][n] = tf32(n < 64 ? Wl2[k][n] : Wr2[k][n-64])
__global__ void cat_w2_kernel(const float* __restrict__ Wl2, const float* __restrict__ Wr2,
                              float* __restrict__ wcat) {
    int i = blockIdx.x * blockDim.x + threadIdx.x;
    if (i >= HIDDIM * 128) return;
    int k = i >> 7, n = i & 127;
    float v = (n < 64) ? Wl2[k * 64 + n] : Wr2[k * 64 + (n - 64)];
    wcat[i] = f2tf32f(v);
}

// ---------------- act (BN+ReLU) in-place + round, optional bf16 -------------
__global__ void act_round_kernel(float4* __restrict__ H, __nv_bfloat162* __restrict__ O2,
                                 int n4, const float* __restrict__ sc, const float* __restrict__ sh) {
    int i = blockIdx.x * blockDim.x + threadIdx.x;
    if (i >= n4) return;
    int c = (i * 4) & (HIDDIM - 1);
    float4 v = H[i];
    v.x = fmaxf(v.x * __ldg(sc + c + 0) + __ldg(sh + c + 0), 0.f);
    v.y = fmaxf(v.y * __ldg(sc + c + 1) + __ldg(sh + c + 1), 0.f);
    v.z = fmaxf(v.z * __ldg(sc + c + 2) + __ldg(sh + c + 2), 0.f);
    v.w = fmaxf(v.w * __ldg(sc + c + 3) + __ldg(sh + c + 3), 0.f);
    if (O2) {
        O2[i * 2 + 0] = __floats2bfloat162_rn(v.x, v.y);
        O2[i * 2 + 1] = __floats2bfloat162_rn(v.z, v.w);
    }
    float4 r;
    r.x = f2tf32f(v.x); r.y = f2tf32f(v.y); r.z = f2tf32f(v.z); r.w = f2tf32f(v.w);
    H[i] = r;
}

// ------------------------- bf16 aggregation (D=256) -------------------------
__global__ void agg256_bf16_kernel(const __nv_bfloat16* __restrict__ Xb, float* __restrict__ Out,
                                   const int* __restrict__ rowptr, const int* __restrict__ csr,
                                   const float* __restrict__ invdeg, int n_nodes) {
    int node = (blockIdx.x * blockDim.x + threadIdx.x) >> 5;
    if (node >= n_nodes) return;
    int lane = threadIdx.x & 31;
    int doff = lane * 8;

    float acc0[8], acc1[8];
#pragma unroll
    for (int i = 0; i < 8; i++) { acc0[i] = 0.f; acc1[i] = 0.f; }

    int beg = rowptr[node];
    int end = rowptr[node + 1];
    int e = beg;

    auto accum = [&](uint4 u, float* acc) {
        __nv_bfloat162 b0 = *reinterpret_cast<__nv_bfloat162*>(&u.x);
        __nv_bfloat162 b1 = *reinterpret_cast<__nv_bfloat162*>(&u.y);
        __nv_bfloat162 b2 = *reinterpret_cast<__nv_bfloat162*>(&u.z);
        __nv_bfloat162 b3 = *reinterpret_cast<__nv_bfloat162*>(&u.w);
        float2 f0 = __bfloat1622float2(b0);
        float2 f1 = __bfloat1622float2(b1);
        float2 f2 = __bfloat1622float2(b2);
        float2 f3 = __bfloat1622float2(b3);
        acc[0] += f0.x; acc[1] += f0.y;
        acc[2] += f1.x; acc[3] += f1.y;
        acc[4] += f2.x; acc[5] += f2.y;
        acc[6] += f3.x; acc[7] += f3.y;
    };

    for (; e + 3 < end; e += 4) {
        int s0 = __ldg(csr + e);
        int s1 = __ldg(csr + e + 1);
        int s2 = __ldg(csr + e + 2);
        int s3 = __ldg(csr + e + 3);
        uint4 u0 = __ldg(reinterpret_cast<const uint4*>(Xb + (size_t)s0 * HIDDIM + doff));
        uint4 u1 = __ldg(reinterpret_cast<const uint4*>(Xb + (size_t)s1 * HIDDIM + doff));
        uint4 u2 = __ldg(reinterpret_cast<const uint4*>(Xb + (size_t)s2 * HIDDIM + doff));
        uint4 u3 = __ldg(reinterpret_cast<const uint4*>(Xb + (size_t)s3 * HIDDIM + doff));
        accum(u0, acc0); accum(u1, acc1); accum(u2, acc0); accum(u3, acc1);
    }
    for (; e < end; e++) {
        int s0 = __ldg(csr + e);
        uint4 u0 = __ldg(reinterpret_cast<const uint4*>(Xb + (size_t)s0 * HIDDIM + doff));
        accum(u0, acc0);
    }

    float w = __ldg(invdeg + node);
    float* o = Out + (size_t)node * HIDDIM + doff;
    float4 o0, o1;
    o0.x = f2tf32f((acc0[0] + acc1[0]) * w);
    o0.y = f2tf32f((acc0[1] + acc1[1]) * w);
    o0.z = f2tf32f((acc0[2] + acc1[2]) * w);
    o0.w = f2tf32f((acc0[3] + acc1[3]) * w);
    o1.x = f2tf32f((acc0[4] + acc1[4]) * w);
    o1.y = f2tf32f((acc0[5] + acc1[5]) * w);
    o1.z = f2tf32f((acc0[6] + acc1[6]) * w);
    o1.w = f2tf32f((acc0[7] + acc1[7]) * w);
    *reinterpret_cast<float4*>(o)     = o0;
    *reinterpret_cast<float4*>(o + 4) = o1;
}

// ------------------------- fp16 aggregation (D=128) -------------------------
// Gathers fp16 rows; fp32 accumulate; output rounded to tf32 (GEMM A operand).
__global__ void agg128_f16_kernel(const __half* __restrict__ Xh, float* __restrict__ Out,
                                  const int* __restrict__ rowptr, const int* __restrict__ csr,
                                  const float* __restrict__ invdeg, int n_nodes) {
    int node = (blockIdx.x * blockDim.x + threadIdx.x) >> 5;
    if (node >= n_nodes) return;
    int lane = threadIdx.x & 31;
    int doff = lane * 4;   // 4 halves = 8 bytes per lane

    float acc0[4], acc1[4];
#pragma unroll
    for (int i = 0; i < 4; i++) { acc0[i] = 0.f; acc1[i] = 0.f; }

    int beg = rowptr[node];
    int end = rowptr[node + 1];
    int e = beg;

    auto accum = [&](uint2 u, float* acc) {
        float2 f0 = __half22float2(*reinterpret_cast<__half2*>(&u.x));
        float2 f1 = __half22float2(*reinterpret_cast<__half2*>(&u.y));
        acc[0] += f0.x; acc[1] += f0.y;
        acc[2] += f1.x; acc[3] += f1.y;
    };

    for (; e + 3 < end; e += 4) {
        int s0 = __ldg(csr + e);
        int s1 = __ldg(csr + e + 1);
        int s2 = __ldg(csr + e + 2);
        int s3 = __ldg(csr + e + 3);
        uint2 u0 = __ldg(reinterpret_cast<const uint2*>(Xh + (size_t)s0 * INDIM + doff));
        uint2 u1 = __ldg(reinterpret_cast<const uint2*>(Xh + (size_t)s1 * INDIM + doff));
        uint2 u2 = __ldg(reinterpret_cast<const uint2*>(Xh + (size_t)s2 * INDIM + doff));
        uint2 u3 = __ldg(reinterpret_cast<const uint2*>(Xh + (size_t)s3 * INDIM + doff));
        accum(u0, acc0); accum(u1, acc1); accum(u2, acc0); accum(u3, acc1);
    }
    for (; e < end; e++) {
        int s0 = __ldg(csr + e);
        uint2 u0 = __ldg(reinterpret_cast<const uint2*>(Xh + (size_t)s0 * INDIM + doff));
        accum(u0, acc0);
    }

    float w = __ldg(invdeg + node);
    float* o = Out + (size_t)node * INDIM + doff;
    float4 ov;
    ov.x = f2tf32f((acc0[0] + acc1[0]) * w);
    ov.y = f2tf32f((acc0[1] + acc1[1]) * w);
    ov.z = f2tf32f((acc0[2] + acc1[2]) * w);
    ov.w = f2tf32f((acc0[3] + acc1[3]) * w);
    *reinterpret_cast<float4*>(o) = ov;
}

// ------------------------- fp16 aggregation (D=64, ADD) ----------------------
__global__ void agg64_f16_kernel(const __half* __restrict__ Yh, float* __restrict__ Out,
                                 const int* __restrict__ rowptr, const int* __restrict__ csr,
                                 const float* __restrict__ invdeg, int n_nodes) {
    int node = (blockIdx.x * blockDim.x + threadIdx.x) >> 5;
    if (node >= n_nodes) return;
    int lane = threadIdx.x & 31;
    int doff = lane * 2;   // 2 halves = 4 bytes per lane

    float a0 = 0.f, a1 = 0.f, b0 = 0.f, b1 = 0.f;

    int beg = rowptr[node];
    int end = rowptr[node + 1];
    int e = beg;

    for (; e + 3 < end; e += 4) {
        int s0 = __ldg(csr + e);
        int s1 = __ldg(csr + e + 1);
        int s2 = __ldg(csr + e + 2);
        int s3 = __ldg(csr + e + 3);
        float2 f0 = __half22float2(*reinterpret_cast<const __half2*>(Yh + (size_t)s0 * OUTDIM + doff));
        float2 f1 = __half22float2(*reinterpret_cast<const __half2*>(Yh + (size_t)s1 * OUTDIM + doff));
        float2 f2 = __half22float2(*reinterpret_cast<const __half2*>(Yh + (size_t)s2 * OUTDIM + doff));
        float2 f3 = __half22float2(*reinterpret_cast<const __half2*>(Yh + (size_t)s3 * OUTDIM + doff));
        a0 += f0.x + f2.x;  b0 += f1.x + f3.x;
        a1 += f0.y + f2.y;  b1 += f1.y + f3.y;
    }
    for (; e < end; e++) {
        int s0 = __ldg(csr + e);
        float2 f0 = __half22float2(*reinterpret_cast<const __half2*>(Yh + (size_t)s0 * OUTDIM + doff));
        a0 += f0.x; a1 += f0.y;
    }

    float w = __ldg(invdeg + node);
    float* o = Out + (size_t)node * OUTDIM + doff;
    o[0] += (a0 + b0) * w;
    o[1] += (a1 + b1) * w;
}

// ------------------------------ TF32 GEMM v2 ---------------------------------
__device__ __forceinline__ void mma_tf32(float c[4], const unsigned a[4], const unsigned b[2]) {
    asm volatile(
        "mma.sync.aligned.m16n8k8.row.col.f32.tf32.tf32.f32 "
        "{%0,%1,%2,%3}, {%4,%5,%6,%7}, {%8,%9}, {%0,%1,%2,%3};"
        : "+f"(c[0]), "+f"(c[1]), "+f"(c[2]), "+f"(c[3])
        : "r"(a[0]), "r"(a[1]), "r"(a[2]), "r"(a[3]), "r"(b[0]), "r"(b[1]));
}

// C = A0@B0 (+ A1@B1) (+ bias). Inputs pre-rounded tf32-in-fp32.
// Split mode (Cy != null, BN==128): cols [0,64) -> Cy as fp16 (row stride 64),
// cols [64,128) -> C float (row stride 64) + bias[col-64].
template <int BM, int BN, int WM, int WN>
__global__ void __launch_bounds__(256, 2)
gemm_tf32(const float* __restrict__ A0, const float* __restrict__ B0g,
          const float* __restrict__ A1, const float* __restrict__ B1g,
          float* __restrict__ C, __half* __restrict__ Cy,
          int M, int N, int K, const float* __restrict__ bias) {
    constexpr int BK = 32, THREADS = 256;
    constexpr int WCOLS = BN / WN;
    constexpr int MT = WM / 16, NT = WN / 8;
    constexpr int AST = BK + 4;
    constexpr int BST = BN + 8;
    constexpr int ACH = (BM * BK) / (4 * THREADS);
    constexpr int BCH = (BK * BN) / (4 * THREADS);
    constexpr int BROWCH = BN / 4;
    constexpr int ABUF = BM * AST;
    constexpr int BBUF = BK * BST;
    static_assert((BM / WM) * (BN / WN) == 8, "8 warps");

    extern __shared__ float smem_f[];
    float* Asm = smem_f;
    float* Bsm = smem_f + 2 * ABUF;

    int tid = threadIdx.x, lane = tid & 31, warp = tid >> 5;
    int wrow = warp / WCOLS, wcol = warp % WCOLS;
    int block_m = blockIdx.y * BM, block_n = blockIdx.x * BN;
    int g = lane >> 2, q = lane & 3;

    uint32_t AsmAddr = (uint32_t)__cvta_generic_to_shared(Asm);
    uint32_t BsmAddr = (uint32_t)__cvta_generic_to_shared(Bsm);

    float acc[MT][NT][4];
#pragma unroll
    for (int mt = 0; mt < MT; mt++)
#pragma unroll
        for (int nt = 0; nt < NT; nt++)
#pragma unroll
            for (int r = 0; r < 4; r++) acc[mt][nt][r] = 0.0f;

    const int kiters = K / BK;
    const int npass = A1 ? 2 : 1;
    const int total = npass * kiters;

    auto issue_stage = [&](int it, int buf) {
        int pass = it / kiters;
        int k0 = (it - pass * kiters) * BK;
        const float* Ap = pass ? A1 : A0;
        const float* Bp = pass ? B1g : B0g;
#pragma unroll
        for (int i = 0; i < ACH; i++) {
            int chunk = tid + i * THREADS;
            int r = chunk >> 3;
            int c4 = (chunk & 7) << 2;
            int gr = block_m + r;
            uint32_t dst = AsmAddr + (buf * ABUF + r * AST + c4) * 4;
            cp_async16(dst, Ap + (size_t)gr * K + k0 + c4, gr < M);
        }
#pragma unroll
        for (int i = 0; i < BCH; i++) {
            int chunk = tid + i * THREADS;
            int r = chunk / BROWCH;
            int c4 = (chunk % BROWCH) * 4;
            uint32_t dst = BsmAddr + (buf * BBUF + r * BST + c4) * 4;
            cp_async16(dst, Bp + (size_t)(k0 + r) * N + block_n + c4, true);
        }
        cp_commit();
    };

    issue_stage(0, 0);
    int buf = 0;
    for (int it = 0; it < total; ++it) {
        cp_wait0();
        __syncthreads();
        if (it + 1 < total) issue_stage(it + 1, buf ^ 1);

        const float* Ab = Asm + buf * ABUF;
        const float* Bb = Bsm + buf * BBUF;
#pragma unroll
        for (int s = 0; s < BK / 8; ++s) {
            int kq = s * 8 + q;
            unsigned af[MT][4], bf[NT][2];
#pragma unroll
            for (int mt = 0; mt < MT; ++mt) {
                int m = wrow * WM + mt * 16 + g;
                af[mt][0] = __float_as_uint(Ab[m * AST + kq]);
                af[mt][1] = __float_as_uint(Ab[(m + 8) * AST + kq]);
                af[mt][2] = __float_as_uint(Ab[m * AST + kq + 4]);
                af[mt][3] = __float_as_uint(Ab[(m + 8) * AST + kq + 4]);
            }
#pragma unroll
            for (int nt = 0; nt < NT; ++nt) {
                int nn = wcol * WN + nt * 8 + g;
                bf[nt][0] = __float_as_uint(Bb[kq * BST + nn]);
                bf[nt][1] = __float_as_uint(Bb[(kq + 4) * BST + nn]);
            }
#pragma unroll
            for (int mt = 0; mt < MT; ++mt)
#pragma unroll
                for (int nt = 0; nt < NT; ++nt)
                    mma_tf32(acc[mt][nt], af[mt], bf[nt]);
        }
        buf ^= 1;
    }

#pragma unroll
    for (int mt = 0; mt < MT; ++mt) {
        int r0 = block_m + wrow * WM + mt * 16 + g;
        int r1 = r0 + 8;
#pragma unroll
        for (int nt = 0; nt < NT; ++nt) {
            int cn = block_n + wcol * WN + nt * 8 + q * 2;
            if (Cy) {
                // split epilogue: N==128, y cols [0,64) fp16, out cols [64,128)
                if (cn < 64) {
                    if (r0 < M)
                        *reinterpret_cast<__half2*>(Cy + (size_t)r0 * 64 + cn) =
                            __floats2half2_rn(acc[mt][nt][0], acc[mt][nt][1]);
                    if (r1 < M)
                        *reinterpret_cast<__half2*>(Cy + (size_t)r1 * 64 + cn) =
                            __floats2half2_rn(acc[mt][nt][2], acc[mt][nt][3]);
                } else {
                    int co = cn - 64;
                    float b0 = __ldg(bias + co), b1 = __ldg(bias + co + 1);
                    if (r0 < M) {
                        float2 t0 = make_float2(acc[mt][nt][0] + b0, acc[mt][nt][1] + b1);
                        *reinterpret_cast<float2*>(C + (size_t)r0 * 64 + co) = t0;
                    }
                    if (r1 < M) {
                        float2 t1 = make_float2(acc[mt][nt][2] + b0, acc[mt][nt][3] + b1);
                        *reinterpret_cast<float2*>(C + (size_t)r1 * 64 + co) = t1;
                    }
                }
            } else {
                float b0 = 0.f, b1 = 0.f;
                if (bias) { b0 = __ldg(bias + cn); b1 = __ldg(bias + cn + 1); }
                if (r0 < M) {
                    float2 t0 = make_float2(acc[mt][nt][0] + b0, acc[mt][nt][1] + b1);
                    *reinterpret_cast<float2*>(C + (size_t)r0 * N + cn) = t0;
                }
                if (r1 < M) {
                    float2 t1 = make_float2(acc[mt][nt][2] + b0, acc[mt][nt][3] + b1);
                    *reinterpret_cast<float2*>(C + (size_t)r1 * N + cn) = t1;
                }
            }
        }
    }
}

// ------------------------------- BatchNorm ----------------------------------
__global__ void colstats_partial(const float* __restrict__ H, int M,
                                 float* __restrict__ ps, float* __restrict__ pq) {
    int c = threadIdx.x;
    float s = 0.f, q = 0.f;
    for (int r = blockIdx.x; r < M; r += gridDim.x) {
        float v = H[(size_t)r * HIDDIM + c];
        s += v;
        q += v * v;
    }
    ps[blockIdx.x * HIDDIM + c] = s;
    pq[blockIdx.x * HIDDIM + c] = q;
}

__global__ void colstats_final(const float* __restrict__ ps, const float* __restrict__ pq,
                               int nb, float inv_m,
                               const float* __restrict__ g, const float* __restrict__ be,
                               float* __restrict__ scale, float* __restrict__ shift) {
    int c = threadIdx.x;
    float s = 0.f, q = 0.f;
    for (int b = 0; b < nb; b++) {
        s += ps[b * HIDDIM + c];
        q += pq[b * HIDDIM + c];
    }
    float mu  = s * inv_m;
    float var = q * inv_m - mu * mu;
    float rs  = rsqrtf(var + 1e-5f);
    float sc  = g[c] * rs;
    scale[c] = sc;
    shift[c] = be[c] - mu * sc;
}

// --------------------------------- launch -----------------------------------
extern "C" void kernel_launch(void* const* d_in, const int* in_sizes, int n_in,
                              void* d_out, int out_size) {
    const float* x   = (const float*)d_in[0];
    const int*   ei  = (const int*)d_in[1];
    const float* Wl0 = (const float*)d_in[2];
    const float* bl0 = (const float*)d_in[3];
    const float* Wr0 = (const float*)d_in[4];
    const float* Wl1 = (const float*)d_in[5];
    const float* bl1 = (const float*)d_in[6];
    const float* Wr1 = (const float*)d_in[7];
    const float* Wl2 = (const float*)d_in[8];
    const float* bl2 = (const float*)d_in[9];
    const float* Wr2 = (const float*)d_in[10];
    const float* g0  = (const float*)d_in[11];
    const float* be0 = (const float*)d_in[12];
    const float* g1  = (const float*)d_in[13];
    const float* be1 = (const float*)d_in[14];
    float* out = (float*)d_out;

    const int N  = NNODES;
    const int NE = NEDGES;

    float *agg, *h1, *h2, *xr, *invdeg, *ps, *pq, *scale, *shift;
    float *wl0r, *wr0r, *wl1r, *wr1r, *wcat;
    __half *xh, *yh;
    __nv_bfloat16* h1b;
    int *cnt, *rowptr, *fill, *csr;
    cudaGetSymbolAddress((void**)&agg,    g_agg);
    cudaGetSymbolAddress((void**)&h1,     g_h1);
    cudaGetSymbolAddress((void**)&h2,     g_h2);
    cudaGetSymbolAddress((void**)&xr,     g_xr);
    cudaGetSymbolAddress((void**)&xh,     g_xh);
    cudaGetSymbolAddress((void**)&yh,     g_yh);
    cudaGetSymbolAddress((void**)&h1b,    g_h1b);
    cudaGetSymbolAddress((void**)&wl0r,   g_wl0r);
    cudaGetSymbolAddress((void**)&wr0r,   g_wr0r);
    cudaGetSymbolAddress((void**)&wl1r,   g_wl1r);
    cudaGetSymbolAddress((void**)&wr1r,   g_wr1r);
    cudaGetSymbolAddress((void**)&wcat,   g_wcat);
    cudaGetSymbolAddress((void**)&invdeg, g_invdeg);
    cudaGetSymbolAddress((void**)&cnt,    g_cnt);
    cudaGetSymbolAddress((void**)&rowptr, g_rowptr);
    cudaGetSymbolAddress((void**)&fill,   g_fill);
    cudaGetSymbolAddress((void**)&csr,    g_csr);
    cudaGetSymbolAddress((void**)&ps,     g_ps);
    cudaGetSymbolAddress((void**)&pq,     g_pq);
    cudaGetSymbolAddress((void**)&scale,  g_scale);
    cudaGetSymbolAddress((void**)&shift,  g_shift);

    const int SMEM_BIG = (2 * 128 * 36 + 2 * 32 * 136) * 4;  // 71680 B
    static int smem_set = 0;
    if (!smem_set) {
        cudaFuncSetAttribute(gemm_tf32<128, 128, 64, 32>,
                             cudaFuncAttributeMaxDynamicSharedMemorySize, SMEM_BIG);
        smem_set = 1;
    }

    dim3 gridBig(HIDDIM / 128, (N + 127) / 128);    // N-dim 256
    dim3 gridL2(1, (N + 127) / 128);                // N-dim 128 (fused layer 2)
    const int AGG_BLOCKS = (N + 7) / 8;

    // ---- CSR build + prologue ----
    zero_int_kernel<<<(N + 255) / 256, 256>>>(cnt, N);
    hist_kernel<<<(NE + 255) / 256, 256>>>(ei, NE, cnt);
    scan_prep_kernel<<<1, 1024>>>(cnt, rowptr, fill, invdeg, N);
    scatter_kernel<<<(NE + 255) / 256, 256>>>(ei, NE, fill, csr);
    round_x_kernel<<<(N * INDIM / 4 + 255) / 256, 256>>>(
        (const float4*)x, (float4*)xr, (__half2*)xh, N * INDIM / 4);
    round_tf32_kernel<<<(INDIM * HIDDIM / 4 + 255) / 256, 256>>>((const float4*)Wl0, (float4*)wl0r, INDIM * HIDDIM / 4);
    round_tf32_kernel<<<(INDIM * HIDDIM / 4 + 255) / 256, 256>>>((const float4*)Wr0, (float4*)wr0r, INDIM * HIDDIM / 4);
    round_tf32_kernel<<<(HIDDIM * HIDDIM / 4 + 255) / 256, 256>>>((const float4*)Wl1, (float4*)wl1r, HIDDIM * HIDDIM / 4);
    round_tf32_kernel<<<(HIDDIM * HIDDIM / 4 + 255) / 256, 256>>>((const float4*)Wr1, (float4*)wr1r, HIDDIM * HIDDIM / 4);
    cat_w2_kernel<<<(HIDDIM * 128 + 255) / 256, 256>>>(Wl2, Wr2, wcat);

    // ---- Layer 0: h1 = mean_agg(x) @ Wl0 + x @ Wr0 + bl0 ----
    agg128_f16_kernel<<<AGG_BLOCKS, 256>>>(xh, agg, rowptr, csr, invdeg, N);
    gemm_tf32<128, 128, 64, 32><<<gridBig, 256, SMEM_BIG>>>(
        agg, wl0r, xr, wr0r, h1, nullptr, N, HIDDIM, INDIM, bl0);
    colstats_partial<<<NB_STATS, HIDDIM>>>(h1, N, ps, pq);
    colstats_final<<<1, HIDDIM>>>(ps, pq, NB_STATS, 1.0f / (float)N, g0, be0, scale, shift);

    // ---- Layer 1: h2 = mean_agg(act0(h1)) @ Wl1 + act0(h1) @ Wr1 + bl1 ----
    act_round_kernel<<<(N * HIDDIM / 4 + 255) / 256, 256>>>(
        (float4*)h1, (__nv_bfloat162*)h1b, N * HIDDIM / 4, scale, shift);
    agg256_bf16_kernel<<<AGG_BLOCKS, 256>>>(h1b, agg, rowptr, csr, invdeg, N);
    gemm_tf32<128, 128, 64, 32><<<gridBig, 256, SMEM_BIG>>>(
        agg, wl1r, h1, wr1r, h2, nullptr, N, HIDDIM, HIDDIM, bl1);
    colstats_partial<<<NB_STATS, HIDDIM>>>(h2, N, ps, pq);
    colstats_final<<<1, HIDDIM>>>(ps, pq, NB_STATS, 1.0f / (float)N, g1, be1, scale, shift);

    // ---- Layer 2 (fused): [y | out] = act1(h2) @ [Wl2 | Wr2]; y fp16 ----
    act_round_kernel<<<(N * HIDDIM / 4 + 255) / 256, 256>>>(
        (float4*)h2, nullptr, N * HIDDIM / 4, scale, shift);
    gemm_tf32<128, 128, 64, 32><<<gridL2, 256, SMEM_BIG>>>(
        h2, wcat, nullptr, nullptr, out, yh, N, 128, HIDDIM, bl2);
    agg64_f16_kernel<<<AGG_BLOCKS, 256>>>(yh, out, rowptr, csr, invdeg, N);
}

// round 11
// speedup vs baseline: 1.7773x; 1.2143x over previous
#include <cuda_runtime.h>
#include <cuda_fp16.h>
#include <cstdint>

// ---------------------------------------------------------------------------
// GraphSAGE (3x SAGEConv + BN/ReLU) on B200 / sm_100a.
//   - fp16 end-to-end GEMM datapath: fp16 has the SAME 10-bit mantissa as the
//     tf32 previously used, so mma.m16n8k16.f16 (2x tensor throughput, half
//     the smem traffic) costs no additional precision. fp32 accumulate.
//   - One fp16 tensor per activation serves both the CSR gather and the GEMM.
//   - Weights pre-transposed [n][k] fp16 -> contiguous B-fragment LDS.
//   - Layer-2: single fused N=128 GEMM over [Wl2|Wr2]^T; split epilogue.
// ---------------------------------------------------------------------------

#define NNODES 50000
#define NEDGES 1600000
#define INDIM  128
#define HIDDIM 256
#define OUTDIM 64
#define NB_STATS 512

// ------------------------- scratch (device globals) ------------------------
__device__ float g_h1 [(size_t)NNODES * HIDDIM];
__device__ float g_h2 [(size_t)NNODES * HIDDIM];
__device__ __align__(16) __half g_aggh[(size_t)NNODES * HIDDIM];  // fp16 agg out
__device__ __align__(16) __half g_xh  [(size_t)NNODES * INDIM];   // fp16 x
__device__ __align__(16) __half g_h1h [(size_t)NNODES * HIDDIM];  // fp16 act0(h1)
__device__ __align__(16) __half g_h2h [(size_t)NNODES * HIDDIM];  // fp16 act1(h2)
__device__ __align__(16) __half g_yh  [(size_t)NNODES * OUTDIM];  // fp16 y
__device__ __align__(16) __half g_wl0t[HIDDIM * INDIM];           // [n][k]
__device__ __align__(16) __half g_wr0t[HIDDIM * INDIM];
__device__ __align__(16) __half g_wl1t[HIDDIM * HIDDIM];
__device__ __align__(16) __half g_wr1t[HIDDIM * HIDDIM];
__device__ __align__(16) __half g_wcatt[128 * HIDDIM];            // [Wl2|Wr2]^T
__device__ float g_invdeg[NNODES];
__device__ int   g_cnt[NNODES];
__device__ int   g_rowptr[NNODES + 1];
__device__ int   g_fill[NNODES];
__device__ int   g_csr[NEDGES];
__device__ float g_ps[NB_STATS * HIDDIM];
__device__ float g_pq[NB_STATS * HIDDIM];
__device__ __align__(16) float g_scale[HIDDIM];
__device__ __align__(16) float g_shift[HIDDIM];

// ------------------------------ cp.async utils ------------------------------
__device__ __forceinline__ void cp_async16(uint32_t saddr, const void* gptr, bool pred) {
    int sz = pred ? 16 : 0;
    asm volatile("cp.async.cg.shared.global [%0], [%1], 16, %2;\n"
                 :: "r"(saddr), "l"(gptr), "r"(sz));
}
__device__ __forceinline__ void cp_commit() {
    asm volatile("cp.async.commit_group;\n" ::: "memory");
}
__device__ __forceinline__ void cp_wait0() {
    asm volatile("cp.async.wait_group 0;\n" ::: "memory");
}

// ------------------------------- CSR build ---------------------------------
__global__ void zero_int_kernel(int* p, int n) {
    int i = blockIdx.x * blockDim.x + threadIdx.x;
    if (i < n) p[i] = 0;
}

__global__ void hist_kernel(const int* __restrict__ ei, int ne, int* __restrict__ cnt) {
    int e = blockIdx.x * blockDim.x + threadIdx.x;
    if (e < ne) {
        int d = ei[ne + e];
        if ((unsigned)d < (unsigned)NNODES)
            atomicAdd(&cnt[d], 1);
    }
}

__global__ void scan_prep_kernel(const int* __restrict__ cnt, int* __restrict__ rowptr,
                                 int* __restrict__ fill, float* __restrict__ invdeg, int n) {
    __shared__ int wsum[32];
    __shared__ int carry_s;
    int tid = threadIdx.x, lane = tid & 31, wid = tid >> 5;
    if (tid == 0) { carry_s = 0; rowptr[0] = 0; }
    __syncthreads();
    for (int base = 0; base < n; base += 1024) {
        int i = base + tid;
        int v = (i < n) ? cnt[i] : 0;
        int s = v;
#pragma unroll
        for (int off = 1; off < 32; off <<= 1) {
            int t = __shfl_up_sync(0xffffffffu, s, off);
            if (lane >= off) s += t;
        }
        if (lane == 31) wsum[wid] = s;
        __syncthreads();
        if (wid == 0) {
            int w = wsum[lane];
#pragma unroll
            for (int off = 1; off < 32; off <<= 1) {
                int t = __shfl_up_sync(0xffffffffu, w, off);
                if (lane >= off) w += t;
            }
            wsum[lane] = w;
        }
        __syncthreads();
        int incl = s + (wid ? wsum[wid - 1] : 0) + carry_s;
        if (i < n) {
            rowptr[i + 1] = incl;
            fill[i] = incl - v;
            invdeg[i] = 1.0f / (float)(v > 0 ? v : 1);
        }
        __syncthreads();
        if (tid == 1023) carry_s = incl;
        __syncthreads();
    }
}

__global__ void scatter_kernel(const int* __restrict__ ei, int ne,
                               int* __restrict__ fill, int* __restrict__ csr) {
    int e = blockIdx.x * blockDim.x + threadIdx.x;
    if (e < ne) {
        int s = ei[e];
        int d = ei[ne + e];
        if ((unsigned)d < (unsigned)NNODES && (unsigned)s < (unsigned)NNODES) {
            int pos = atomicAdd(&fill[d], 1);
            if ((unsigned)pos < (unsigned)NEDGES)
                csr[pos] = s;
        }
    }
}

// ----------------------------- prologue kernels ------------------------------
// x -> fp16
__global__ void x_f16_kernel(const float4* __restrict__ src, __half2* __restrict__ dh2, int n4) {
    int i = blockIdx.x * blockDim.x + threadIdx.x;
    if (i >= n4) return;
    float4 v = src[i];
    dh2[i * 2 + 0] = __floats2half2_rn(v.x, v.y);
    dh2[i * 2 + 1] = __floats2half2_rn(v.z, v.w);
}

// Wt[n][k] = fp16(W[k][n]);  W is [K][N] row-major
__global__ void wt_f16_kernel(const float* __restrict__ W, __half* __restrict__ Wt, int K, int N) {
    int i = blockIdx.x * blockDim.x + threadIdx.x;
    if (i >= K * N) return;
    int n = i / K, k = i - n * K;
    Wt[i] = __float2half_rn(W[k * N + n]);
}

// wcatt[n][k]: n<64 -> Wl2[k][n], else Wr2[k][n-64]. Both [K][64] row-major.
__global__ void cat_w2t_kernel(const float* __restrict__ Wl2, const float* __restrict__ Wr2,
                               __half* __restrict__ Wt, int K) {
    int i = blockIdx.x * blockDim.x + threadIdx.x;
    if (i >= 128 * K) return;
    int n = i / K, k = i - n * K;
    float v = (n < 64) ? Wl2[k * 64 + n] : Wr2[k * 64 + (n - 64)];
    Wt[i] = __float2half_rn(v);
}

// ------------------ act (BN+ReLU) -> fp16 (gather + GEMM A) ------------------
__global__ void act_f16_kernel(const float4* __restrict__ H, __half2* __restrict__ O2,
                               int n4, const float* __restrict__ sc, const float* __restrict__ sh) {
    int i = blockIdx.x * blockDim.x + threadIdx.x;
    if (i >= n4) return;
    int c = (i * 4) & (HIDDIM - 1);
    float4 v = H[i];
    v.x = fmaxf(v.x * __ldg(sc + c + 0) + __ldg(sh + c + 0), 0.f);
    v.y = fmaxf(v.y * __ldg(sc + c + 1) + __ldg(sh + c + 1), 0.f);
    v.z = fmaxf(v.z * __ldg(sc + c + 2) + __ldg(sh + c + 2), 0.f);
    v.w = fmaxf(v.w * __ldg(sc + c + 3) + __ldg(sh + c + 3), 0.f);
    O2[i * 2 + 0] = __floats2half2_rn(v.x, v.y);
    O2[i * 2 + 1] = __floats2half2_rn(v.z, v.w);
}

// ------------------------- fp16 aggregation (D=256) --------------------------
// Gathers fp16, fp32 accumulate, writes fp16 (GEMM A operand).
__global__ void agg256_f16_kernel(const __half* __restrict__ Xh, __half* __restrict__ Out,
                                  const int* __restrict__ rowptr, const int* __restrict__ csr,
                                  const float* __restrict__ invdeg, int n_nodes) {
    int node = (blockIdx.x * blockDim.x + threadIdx.x) >> 5;
    if (node >= n_nodes) return;
    int lane = threadIdx.x & 31;
    int doff = lane * 8;

    float acc0[8], acc1[8];
#pragma unroll
    for (int i = 0; i < 8; i++) { acc0[i] = 0.f; acc1[i] = 0.f; }

    int beg = rowptr[node];
    int end = rowptr[node + 1];
    int e = beg;

    auto accum = [&](uint4 u, float* acc) {
        float2 f0 = __half22float2(*reinterpret_cast<__half2*>(&u.x));
        float2 f1 = __half22float2(*reinterpret_cast<__half2*>(&u.y));
        float2 f2 = __half22float2(*reinterpret_cast<__half2*>(&u.z));
        float2 f3 = __half22float2(*reinterpret_cast<__half2*>(&u.w));
        acc[0] += f0.x; acc[1] += f0.y;
        acc[2] += f1.x; acc[3] += f1.y;
        acc[4] += f2.x; acc[5] += f2.y;
        acc[6] += f3.x; acc[7] += f3.y;
    };

    for (; e + 3 < end; e += 4) {
        int s0 = __ldg(csr + e);
        int s1 = __ldg(csr + e + 1);
        int s2 = __ldg(csr + e + 2);
        int s3 = __ldg(csr + e + 3);
        uint4 u0 = __ldg(reinterpret_cast<const uint4*>(Xh + (size_t)s0 * HIDDIM + doff));
        uint4 u1 = __ldg(reinterpret_cast<const uint4*>(Xh + (size_t)s1 * HIDDIM + doff));
        uint4 u2 = __ldg(reinterpret_cast<const uint4*>(Xh + (size_t)s2 * HIDDIM + doff));
        uint4 u3 = __ldg(reinterpret_cast<const uint4*>(Xh + (size_t)s3 * HIDDIM + doff));
        accum(u0, acc0); accum(u1, acc1); accum(u2, acc0); accum(u3, acc1);
    }
    for (; e < end; e++) {
        int s0 = __ldg(csr + e);
        uint4 u0 = __ldg(reinterpret_cast<const uint4*>(Xh + (size_t)s0 * HIDDIM + doff));
        accum(u0, acc0);
    }

    float w = __ldg(invdeg + node);
    uint4 ov;
    __half2 h0 = __floats2half2_rn((acc0[0] + acc1[0]) * w, (acc0[1] + acc1[1]) * w);
    __half2 h1v = __floats2half2_rn((acc0[2] + acc1[2]) * w, (acc0[3] + acc1[3]) * w);
    __half2 h2v = __floats2half2_rn((acc0[4] + acc1[4]) * w, (acc0[5] + acc1[5]) * w);
    __half2 h3 = __floats2half2_rn((acc0[6] + acc1[6]) * w, (acc0[7] + acc1[7]) * w);
    ov.x = *reinterpret_cast<uint32_t*>(&h0);
    ov.y = *reinterpret_cast<uint32_t*>(&h1v);
    ov.z = *reinterpret_cast<uint32_t*>(&h2v);
    ov.w = *reinterpret_cast<uint32_t*>(&h3);
    *reinterpret_cast<uint4*>(Out + (size_t)node * HIDDIM + doff) = ov;
}

// ------------------------- fp16 aggregation (D=128) --------------------------
__global__ void agg128_f16_kernel(const __half* __restrict__ Xh, __half* __restrict__ Out,
                                  const int* __restrict__ rowptr, const int* __restrict__ csr,
                                  const float* __restrict__ invdeg, int n_nodes) {
    int node = (blockIdx.x * blockDim.x + threadIdx.x) >> 5;
    if (node >= n_nodes) return;
    int lane = threadIdx.x & 31;
    int doff = lane * 4;

    float acc0[4], acc1[4];
#pragma unroll
    for (int i = 0; i < 4; i++) { acc0[i] = 0.f; acc1[i] = 0.f; }

    int beg = rowptr[node];
    int end = rowptr[node + 1];
    int e = beg;

    auto accum = [&](uint2 u, float* acc) {
        float2 f0 = __half22float2(*reinterpret_cast<__half2*>(&u.x));
        float2 f1 = __half22float2(*reinterpret_cast<__half2*>(&u.y));
        acc[0] += f0.x; acc[1] += f0.y;
        acc[2] += f1.x; acc[3] += f1.y;
    };

    for (; e + 3 < end; e += 4) {
        int s0 = __ldg(csr + e);
        int s1 = __ldg(csr + e + 1);
        int s2 = __ldg(csr + e + 2);
        int s3 = __ldg(csr + e + 3);
        uint2 u0 = __ldg(reinterpret_cast<const uint2*>(Xh + (size_t)s0 * INDIM + doff));
        uint2 u1 = __ldg(reinterpret_cast<const uint2*>(Xh + (size_t)s1 * INDIM + doff));
        uint2 u2 = __ldg(reinterpret_cast<const uint2*>(Xh + (size_t)s2 * INDIM + doff));
        uint2 u3 = __ldg(reinterpret_cast<const uint2*>(Xh + (size_t)s3 * INDIM + doff));
        accum(u0, acc0); accum(u1, acc1); accum(u2, acc0); accum(u3, acc1);
    }
    for (; e < end; e++) {
        int s0 = __ldg(csr + e);
        uint2 u0 = __ldg(reinterpret_cast<const uint2*>(Xh + (size_t)s0 * INDIM + doff));
        accum(u0, acc0);
    }

    float w = __ldg(invdeg + node);
    __half2 h0 = __floats2half2_rn((acc0[0] + acc1[0]) * w, (acc0[1] + acc1[1]) * w);
    __half2 h1v = __floats2half2_rn((acc0[2] + acc1[2]) * w, (acc0[3] + acc1[3]) * w);
    uint2 ov;
    ov.x = *reinterpret_cast<uint32_t*>(&h0);
    ov.y = *reinterpret_cast<uint32_t*>(&h1v);
    *reinterpret_cast<uint2*>(Out + (size_t)node * INDIM + doff) = ov;
}

// ------------------------- fp16 aggregation (D=64, ADD) ----------------------
__global__ void agg64_f16_kernel(const __half* __restrict__ Yh, float* __restrict__ Out,
                                 const int* __restrict__ rowptr, const int* __restrict__ csr,
                                 const float* __restrict__ invdeg, int n_nodes) {
    int node = (blockIdx.x * blockDim.x + threadIdx.x) >> 5;
    if (node >= n_nodes) return;
    int lane = threadIdx.x & 31;
    int doff = lane * 2;

    float a0 = 0.f, a1 = 0.f, b0 = 0.f, b1 = 0.f;

    int beg = rowptr[node];
    int end = rowptr[node + 1];
    int e = beg;

    for (; e + 3 < end; e += 4) {
        int s0 = __ldg(csr + e);
        int s1 = __ldg(csr + e + 1);
        int s2 = __ldg(csr + e + 2);
        int s3 = __ldg(csr + e + 3);
        float2 f0 = __half22float2(*reinterpret_cast<const __half2*>(Yh + (size_t)s0 * OUTDIM + doff));
        float2 f1 = __half22float2(*reinterpret_cast<const __half2*>(Yh + (size_t)s1 * OUTDIM + doff));
        float2 f2 = __half22float2(*reinterpret_cast<const __half2*>(Yh + (size_t)s2 * OUTDIM + doff));
        float2 f3 = __half22float2(*reinterpret_cast<const __half2*>(Yh + (size_t)s3 * OUTDIM + doff));
        a0 += f0.x + f2.x;  b0 += f1.x + f3.x;
        a1 += f0.y + f2.y;  b1 += f1.y + f3.y;
    }
    for (; e < end; e++) {
        int s0 = __ldg(csr + e);
        float2 f0 = __half22float2(*reinterpret_cast<const __half2*>(Yh + (size_t)s0 * OUTDIM + doff));
        a0 += f0.x; a1 += f0.y;
    }

    float w = __ldg(invdeg + node);
    float* o = Out + (size_t)node * OUTDIM + doff;
    o[0] += (a0 + b0) * w;
    o[1] += (a1 + b1) * w;
}

// ------------------------------ FP16 GEMM v3 ---------------------------------
__device__ __forceinline__ void mma_f16(float c[4], const unsigned a[4], const unsigned b[2]) {
    asm volatile(
        "mma.sync.aligned.m16n8k16.row.col.f32.f16.f16.f32 "
        "{%0,%1,%2,%3}, {%4,%5,%6,%7}, {%8,%9}, {%0,%1,%2,%3};"
        : "+f"(c[0]), "+f"(c[1]), "+f"(c[2]), "+f"(c[3])
        : "r"(a[0]), "r"(a[1]), "r"(a[2]), "r"(a[3]), "r"(b[0]), "r"(b[1]));
}

// C = A0@B0t^T (+ A1@B1t^T) (+ bias). A [M][K] fp16 row-major; Bt [N][K] fp16.
// Split mode (Cy != null, N==128): cols [0,64) -> Cy fp16 (stride 64),
// cols [64,128) -> C float (stride 64) + bias[col-64].
// Smem strides 40 halves -> conflict-free 4B fragment LDS (bank = 20g+q+8s).
template <int BM, int BN, int WM, int WN>
__global__ void __launch_bounds__(256, 2)
gemm_f16(const __half* __restrict__ A0, const __half* __restrict__ B0t,
         const __half* __restrict__ A1, const __half* __restrict__ B1t,
         float* __restrict__ C, __half* __restrict__ Cy,
         int M, int N, int K, const float* __restrict__ bias) {
    constexpr int BK = 32, THREADS = 256;
    constexpr int WCOLS = BN / WN;
    constexpr int MT = WM / 16, NT = WN / 8;
    constexpr int AST = BK + 8;                 // 40 halves
    constexpr int BST = BK + 8;                 // 40 halves
    constexpr int ACH = (BM * BK) / (8 * THREADS);   // 16B = 8 halves per cp
    constexpr int BCH = (BN * BK) / (8 * THREADS);
    constexpr int ABUF = BM * AST;              // halves
    constexpr int BBUF = BN * BST;
    static_assert((BM / WM) * (BN / WN) == 8, "8 warps");

    __shared__ __half Asm[2 * ABUF];
    __shared__ __half Bsm[2 * BBUF];

    int tid = threadIdx.x, lane = tid & 31, warp = tid >> 5;
    int wrow = warp / WCOLS, wcol = warp % WCOLS;
    int block_m = blockIdx.y * BM, block_n = blockIdx.x * BN;
    int g = lane >> 2, q = lane & 3;

    uint32_t AsmAddr = (uint32_t)__cvta_generic_to_shared(Asm);
    uint32_t BsmAddr = (uint32_t)__cvta_generic_to_shared(Bsm);

    float acc[MT][NT][4];
#pragma unroll
    for (int mt = 0; mt < MT; mt++)
#pragma unroll
        for (int nt = 0; nt < NT; nt++)
#pragma unroll
            for (int r = 0; r < 4; r++) acc[mt][nt][r] = 0.0f;

    const int kiters = K / BK;
    const int npass = A1 ? 2 : 1;
    const int total = npass * kiters;

    auto issue_stage = [&](int it, int buf) {
        int pass = it / kiters;
        int k0 = (it - pass * kiters) * BK;
        const __half* Ap = pass ? A1 : A0;
        const __half* Bp = pass ? B1t : B0t;
#pragma unroll
        for (int i = 0; i < ACH; i++) {
            int chunk = tid + i * THREADS;
            int r = chunk >> 2;                 // 4 chunks (32 halves) per row
            int c8 = (chunk & 3) << 3;          // half offset
            int gr = block_m + r;
            uint32_t dst = AsmAddr + (buf * ABUF + r * AST + c8) * 2;
            cp_async16(dst, Ap + (size_t)gr * K + k0 + c8, gr < M);
        }
#pragma unroll
        for (int i = 0; i < BCH; i++) {
            int chunk = tid + i * THREADS;
            int r = chunk >> 2;                 // row of Bt tile (n index)
            int c8 = (chunk & 3) << 3;
            uint32_t dst = BsmAddr + (buf * BBUF + r * BST + c8) * 2;
            cp_async16(dst, Bp + (size_t)(block_n + r) * K + k0 + c8, true);
        }
        cp_commit();
    };

    issue_stage(0, 0);
    int buf = 0;
    for (int it = 0; it < total; ++it) {
        cp_wait0();
        __syncthreads();
        if (it + 1 < total) issue_stage(it + 1, buf ^ 1);

        const __half* Ab = Asm + buf * ABUF;
        const __half* Bb = Bsm + buf * BBUF;
#pragma unroll
        for (int s = 0; s < BK / 16; ++s) {
            int kb = s * 16 + q * 2;            // half index
            unsigned af[MT][4], bf[NT][2];
#pragma unroll
            for (int mt = 0; mt < MT; ++mt) {
                int m = wrow * WM + mt * 16 + g;
                af[mt][0] = *reinterpret_cast<const unsigned*>(Ab + m * AST + kb);
                af[mt][1] = *reinterpret_cast<const unsigned*>(Ab + (m + 8) * AST + kb);
                af[mt][2] = *reinterpret_cast<const unsigned*>(Ab + m * AST + kb + 8);
                af[mt][3] = *reinterpret_cast<const unsigned*>(Ab + (m + 8) * AST + kb + 8);
            }
#pragma unroll
            for (int nt = 0; nt < NT; ++nt) {
                int nn = wcol * WN + nt * 8 + g;
                bf[nt][0] = *reinterpret_cast<const unsigned*>(Bb + nn * BST + kb);
                bf[nt][1] = *reinterpret_cast<const unsigned*>(Bb + nn * BST + kb + 8);
            }
#pragma unroll
            for (int mt = 0; mt < MT; ++mt)
#pragma unroll
                for (int nt = 0; nt < NT; ++nt)
                    mma_f16(acc[mt][nt], af[mt], bf[nt]);
        }
        buf ^= 1;
    }

#pragma unroll
    for (int mt = 0; mt < MT; ++mt) {
        int r0 = block_m + wrow * WM + mt * 16 + g;
        int r1 = r0 + 8;
#pragma unroll
        for (int nt = 0; nt < NT; ++nt) {
            int cn = block_n + wcol * WN + nt * 8 + q * 2;
            if (Cy) {
                if (cn < 64) {
                    if (r0 < M)
                        *reinterpret_cast<__half2*>(Cy + (size_t)r0 * 64 + cn) =
                            __floats2half2_rn(acc[mt][nt][0], acc[mt][nt][1]);
                    if (r1 < M)
                        *reinterpret_cast<__half2*>(Cy + (size_t)r1 * 64 + cn) =
                            __floats2half2_rn(acc[mt][nt][2], acc[mt][nt][3]);
                } else {
                    int co = cn - 64;
                    float b0 = __ldg(bias + co), b1 = __ldg(bias + co + 1);
                    if (r0 < M) {
                        float2 t0 = make_float2(acc[mt][nt][0] + b0, acc[mt][nt][1] + b1);
                        *reinterpret_cast<float2*>(C + (size_t)r0 * 64 + co) = t0;
                    }
                    if (r1 < M) {
                        float2 t1 = make_float2(acc[mt][nt][2] + b0, acc[mt][nt][3] + b1);
                        *reinterpret_cast<float2*>(C + (size_t)r1 * 64 + co) = t1;
                    }
                }
            } else {
                float b0 = 0.f, b1 = 0.f;
                if (bias) { b0 = __ldg(bias + cn); b1 = __ldg(bias + cn + 1); }
                if (r0 < M) {
                    float2 t0 = make_float2(acc[mt][nt][0] + b0, acc[mt][nt][1] + b1);
                    *reinterpret_cast<float2*>(C + (size_t)r0 * N + cn) = t0;
                }
                if (r1 < M) {
                    float2 t1 = make_float2(acc[mt][nt][2] + b0, acc[mt][nt][3] + b1);
                    *reinterpret_cast<float2*>(C + (size_t)r1 * N + cn) = t1;
                }
            }
        }
    }
}

// ------------------------------- BatchNorm ----------------------------------
__global__ void colstats_partial(const float* __restrict__ H, int M,
                                 float* __restrict__ ps, float* __restrict__ pq) {
    int c = threadIdx.x;
    float s = 0.f, q = 0.f;
    for (int r = blockIdx.x; r < M; r += gridDim.x) {
        float v = H[(size_t)r * HIDDIM + c];
        s += v;
        q += v * v;
    }
    ps[blockIdx.x * HIDDIM + c] = s;
    pq[blockIdx.x * HIDDIM + c] = q;
}

__global__ void colstats_final(const float* __restrict__ ps, const float* __restrict__ pq,
                               int nb, float inv_m,
                               const float* __restrict__ g, const float* __restrict__ be,
                               float* __restrict__ scale, float* __restrict__ shift) {
    int c = threadIdx.x;
    float s = 0.f, q = 0.f;
    for (int b = 0; b < nb; b++) {
        s += ps[b * HIDDIM + c];
        q += pq[b * HIDDIM + c];
    }
    float mu  = s * inv_m;
    float var = q * inv_m - mu * mu;
    float rs  = rsqrtf(var + 1e-5f);
    float sc  = g[c] * rs;
    scale[c] = sc;
    shift[c] = be[c] - mu * sc;
}

// --------------------------------- launch -----------------------------------
extern "C" void kernel_launch(void* const* d_in, const int* in_sizes, int n_in,
                              void* d_out, int out_size) {
    const float* x   = (const float*)d_in[0];
    const int*   ei  = (const int*)d_in[1];
    const float* Wl0 = (const float*)d_in[2];
    const float* bl0 = (const float*)d_in[3];
    const float* Wr0 = (const float*)d_in[4];
    const float* Wl1 = (const float*)d_in[5];
    const float* bl1 = (const float*)d_in[6];
    const float* Wr1 = (const float*)d_in[7];
    const float* Wl2 = (const float*)d_in[8];
    const float* bl2 = (const float*)d_in[9];
    const float* Wr2 = (const float*)d_in[10];
    const float* g0  = (const float*)d_in[11];
    const float* be0 = (const float*)d_in[12];
    const float* g1  = (const float*)d_in[13];
    const float* be1 = (const float*)d_in[14];
    float* out = (float*)d_out;

    const int N  = NNODES;
    const int NE = NEDGES;

    float *h1, *h2, *invdeg, *ps, *pq, *scale, *shift;
    __half *aggh, *xh, *h1h, *h2h, *yh, *wl0t, *wr0t, *wl1t, *wr1t, *wcatt;
    int *cnt, *rowptr, *fill, *csr;
    cudaGetSymbolAddress((void**)&h1,     g_h1);
    cudaGetSymbolAddress((void**)&h2,     g_h2);
    cudaGetSymbolAddress((void**)&aggh,   g_aggh);
    cudaGetSymbolAddress((void**)&xh,     g_xh);
    cudaGetSymbolAddress((void**)&h1h,    g_h1h);
    cudaGetSymbolAddress((void**)&h2h,    g_h2h);
    cudaGetSymbolAddress((void**)&yh,     g_yh);
    cudaGetSymbolAddress((void**)&wl0t,   g_wl0t);
    cudaGetSymbolAddress((void**)&wr0t,   g_wr0t);
    cudaGetSymbolAddress((void**)&wl1t,   g_wl1t);
    cudaGetSymbolAddress((void**)&wr1t,   g_wr1t);
    cudaGetSymbolAddress((void**)&wcatt,  g_wcatt);
    cudaGetSymbolAddress((void**)&invdeg, g_invdeg);
    cudaGetSymbolAddress((void**)&cnt,    g_cnt);
    cudaGetSymbolAddress((void**)&rowptr, g_rowptr);
    cudaGetSymbolAddress((void**)&fill,   g_fill);
    cudaGetSymbolAddress((void**)&csr,    g_csr);
    cudaGetSymbolAddress((void**)&ps,     g_ps);
    cudaGetSymbolAddress((void**)&pq,     g_pq);
    cudaGetSymbolAddress((void**)&scale,  g_scale);
    cudaGetSymbolAddress((void**)&shift,  g_shift);

    dim3 gridBig(HIDDIM / 128, (N + 127) / 128);    // N-dim 256 -> grid.x 2
    dim3 gridL2(1, (N + 127) / 128);                // fused layer-2: N=128
    const int AGG_BLOCKS = (N + 7) / 8;

    // ---- CSR build + prologue (fp16 conversions / transposes) ----
    zero_int_kernel<<<(N + 255) / 256, 256>>>(cnt, N);
    hist_kernel<<<(NE + 255) / 256, 256>>>(ei, NE, cnt);
    scan_prep_kernel<<<1, 1024>>>(cnt, rowptr, fill, invdeg, N);
    scatter_kernel<<<(NE + 255) / 256, 256>>>(ei, NE, fill, csr);
    x_f16_kernel<<<(N * INDIM / 4 + 255) / 256, 256>>>((const float4*)x, (__half2*)xh, N * INDIM / 4);
    wt_f16_kernel<<<(INDIM * HIDDIM + 255) / 256, 256>>>(Wl0, wl0t, INDIM, HIDDIM);
    wt_f16_kernel<<<(INDIM * HIDDIM + 255) / 256, 256>>>(Wr0, wr0t, INDIM, HIDDIM);
    wt_f16_kernel<<<(HIDDIM * HIDDIM + 255) / 256, 256>>>(Wl1, wl1t, HIDDIM, HIDDIM);
    wt_f16_kernel<<<(HIDDIM * HIDDIM + 255) / 256, 256>>>(Wr1, wr1t, HIDDIM, HIDDIM);
    cat_w2t_kernel<<<(128 * HIDDIM + 255) / 256, 256>>>(Wl2, Wr2, wcatt, HIDDIM);

    // ---- Layer 0: h1 = mean_agg(x) @ Wl0 + x @ Wr0 + bl0 ----
    agg128_f16_kernel<<<AGG_BLOCKS, 256>>>(xh, aggh, rowptr, csr, invdeg, N);
    gemm_f16<128, 128, 64, 32><<<gridBig, 256>>>(
        aggh, wl0t, xh, wr0t, h1, nullptr, N, HIDDIM, INDIM, bl0);
    colstats_partial<<<NB_STATS, HIDDIM>>>(h1, N, ps, pq);
    colstats_final<<<1, HIDDIM>>>(ps, pq, NB_STATS, 1.0f / (float)N, g0, be0, scale, shift);

    // ---- Layer 1: h2 = mean_agg(act0(h1)) @ Wl1 + act0(h1) @ Wr1 + bl1 ----
    act_f16_kernel<<<(N * HIDDIM / 4 + 255) / 256, 256>>>(
        (const float4*)h1, (__half2*)h1h, N * HIDDIM / 4, scale, shift);
    agg256_f16_kernel<<<AGG_BLOCKS, 256>>>(h1h, aggh, rowptr, csr, invdeg, N);
    gemm_f16<128, 128, 64, 32><<<gridBig, 256>>>(
        aggh, wl1t, h1h, wr1t, h2, nullptr, N, HIDDIM, HIDDIM, bl1);
    colstats_partial<<<NB_STATS, HIDDIM>>>(h2, N, ps, pq);
    colstats_final<<<1, HIDDIM>>>(ps, pq, NB_STATS, 1.0f / (float)N, g1, be1, scale, shift);

    // ---- Layer 2 (fused): [y | out] = act1(h2) @ [Wl2 | Wr2]; y fp16 ----
    act_f16_kernel<<<(N * HIDDIM / 4 + 255) / 256, 256>>>(
        (const float4*)h2, (__half2*)h2h, N * HIDDIM / 4, scale, shift);
    gemm_f16<128, 128, 64, 32><<<gridL2, 256>>>(
        h2h, wcatt, nullptr, nullptr, out, yh, N, 128, HIDDIM, bl2);
    agg64_f16_kernel<<<AGG_BLOCKS, 256>>>(yh, out, rowptr, csr, invdeg, N);
}

// round 12
// speedup vs baseline: 2.2368x; 1.2585x over previous
#include <cuda_runtime.h>
#include <cuda_fp16.h>
#include <cstdint>

// ---------------------------------------------------------------------------
// GraphSAGE (3x SAGEConv + BN/ReLU) on B200 / sm_100a.
//   - fp16 end-to-end GEMM datapath (m16n8k16, fp32 accumulate).
//   - BatchNorm column stats fused into the GEMM epilogue (deterministic
//     per-blockIdx.y partials) -> no separate stats passes over h1/h2.
//   - 3-phase parallel CSR scan; single fused weight-prep kernel.
//   - Layer-2: single fused N=128 GEMM over [Wl2|Wr2]^T; split epilogue.
// ---------------------------------------------------------------------------

#define NNODES 50000
#define NEDGES 1600000
#define INDIM  128
#define HIDDIM 256
#define OUTDIM 64
#define NBY    ((NNODES + 127) / 128)   // 391 GEMM row-blocks = stats partials
#define NBLK   ((NNODES + 255) / 256)   // 196 scan blocks

// ------------------------- scratch (device globals) ------------------------
__device__ float g_h1 [(size_t)NNODES * HIDDIM];
__device__ float g_h2 [(size_t)NNODES * HIDDIM];
__device__ __align__(16) __half g_aggh[(size_t)NNODES * HIDDIM];
__device__ __align__(16) __half g_xh  [(size_t)NNODES * INDIM];
__device__ __align__(16) __half g_h1h [(size_t)NNODES * HIDDIM];
__device__ __align__(16) __half g_h2h [(size_t)NNODES * HIDDIM];
__device__ __align__(16) __half g_yh  [(size_t)NNODES * OUTDIM];
__device__ __align__(16) __half g_wl0t[HIDDIM * INDIM];
__device__ __align__(16) __half g_wr0t[HIDDIM * INDIM];
__device__ __align__(16) __half g_wl1t[HIDDIM * HIDDIM];
__device__ __align__(16) __half g_wr1t[HIDDIM * HIDDIM];
__device__ __align__(16) __half g_wcatt[128 * HIDDIM];
__device__ float g_invdeg[NNODES];
__device__ int   g_cnt[NNODES];
__device__ int   g_rowptr[NNODES + 1];
__device__ int   g_fill[NNODES];
__device__ int   g_csr[NEDGES];
__device__ int   g_bsum[NBLK];
__device__ float g_ps[(size_t)NBY * HIDDIM];
__device__ float g_pq[(size_t)NBY * HIDDIM];
__device__ __align__(16) float g_scale[HIDDIM];
__device__ __align__(16) float g_shift[HIDDIM];

// ------------------------------ cp.async utils ------------------------------
__device__ __forceinline__ void cp_async16(uint32_t saddr, const void* gptr, bool pred) {
    int sz = pred ? 16 : 0;
    asm volatile("cp.async.cg.shared.global [%0], [%1], 16, %2;\n"
                 :: "r"(saddr), "l"(gptr), "r"(sz));
}
__device__ __forceinline__ void cp_commit() {
    asm volatile("cp.async.commit_group;\n" ::: "memory");
}
__device__ __forceinline__ void cp_wait0() {
    asm volatile("cp.async.wait_group 0;\n" ::: "memory");
}

// ------------------------------- CSR build ---------------------------------
__global__ void zero_int_kernel(int* p, int n) {
    int i = blockIdx.x * blockDim.x + threadIdx.x;
    if (i < n) p[i] = 0;
}

__global__ void hist_kernel(const int* __restrict__ ei, int ne, int* __restrict__ cnt) {
    int e = blockIdx.x * blockDim.x + threadIdx.x;
    if (e < ne) {
        int d = ei[ne + e];
        if ((unsigned)d < (unsigned)NNODES)
            atomicAdd(&cnt[d], 1);
    }
}

// Phase 1: per-block sums of cnt
__global__ void scan_bsums_kernel(const int* __restrict__ cnt, int* __restrict__ bsum, int n) {
    __shared__ int sh[256];
    int i = blockIdx.x * 256 + threadIdx.x;
    sh[threadIdx.x] = (i < n) ? cnt[i] : 0;
    __syncthreads();
    for (int s = 128; s > 0; s >>= 1) {
        if (threadIdx.x < s) sh[threadIdx.x] += sh[threadIdx.x + s];
        __syncthreads();
    }
    if (threadIdx.x == 0) bsum[blockIdx.x] = sh[0];
}

// Phase 2: exclusive scan of block sums (single block, nb <= 256)
__global__ void scan_offsets_kernel(int* __restrict__ bsum, int nb) {
    __shared__ int wsum[8];
    int t = threadIdx.x, lane = t & 31, wid = t >> 5;
    int v = (t < nb) ? bsum[t] : 0;
    int s = v;
#pragma unroll
    for (int off = 1; off < 32; off <<= 1) {
        int u = __shfl_up_sync(0xffffffffu, s, off);
        if (lane >= off) s += u;
    }
    if (lane == 31) wsum[wid] = s;
    __syncthreads();
    if (wid == 0 && lane < 8) {
        int w = wsum[lane];
#pragma unroll
        for (int off = 1; off < 8; off <<= 1) {
            int u = __shfl_up_sync(0xffu, w, off);
            if (lane >= off) w += u;
        }
        wsum[lane] = w;
    }
    __syncthreads();
    int incl = s + (wid ? wsum[wid - 1] : 0);
    if (t < nb) bsum[t] = incl - v;   // exclusive block offset
}

// Phase 3: per-block scan + offsets -> rowptr / fill / invdeg
__global__ void scan_final_kernel(const int* __restrict__ cnt, const int* __restrict__ boff,
                                  int* __restrict__ rowptr, int* __restrict__ fill,
                                  float* __restrict__ invdeg, int n) {
    __shared__ int wsum[8];
    int i = blockIdx.x * 256 + threadIdx.x;
    int lane = threadIdx.x & 31, wid = threadIdx.x >> 5;
    int v = (i < n) ? cnt[i] : 0;
    int s = v;
#pragma unroll
    for (int off = 1; off < 32; off <<= 1) {
        int u = __shfl_up_sync(0xffffffffu, s, off);
        if (lane >= off) s += u;
    }
    if (lane == 31) wsum[wid] = s;
    __syncthreads();
    if (wid == 0 && lane < 8) {
        int w = wsum[lane];
#pragma unroll
        for (int off = 1; off < 8; off <<= 1) {
            int u = __shfl_up_sync(0xffu, w, off);
            if (lane >= off) w += u;
        }
        wsum[lane] = w;
    }
    __syncthreads();
    int incl = s + (wid ? wsum[wid - 1] : 0) + boff[blockIdx.x];
    if (i < n) {
        rowptr[i + 1] = incl;
        fill[i] = incl - v;
        invdeg[i] = 1.0f / (float)(v > 0 ? v : 1);
    }
    if (i == 0) rowptr[0] = 0;
}

__global__ void scatter_kernel(const int* __restrict__ ei, int ne,
                               int* __restrict__ fill, int* __restrict__ csr) {
    int e = blockIdx.x * blockDim.x + threadIdx.x;
    if (e < ne) {
        int s = ei[e];
        int d = ei[ne + e];
        if ((unsigned)d < (unsigned)NNODES && (unsigned)s < (unsigned)NNODES) {
            int pos = atomicAdd(&fill[d], 1);
            if ((unsigned)pos < (unsigned)NEDGES)
                csr[pos] = s;
        }
    }
}

// ----------------------------- prologue kernels ------------------------------
__global__ void x_f16_kernel(const float4* __restrict__ src, __half2* __restrict__ dh2, int n4) {
    int i = blockIdx.x * blockDim.x + threadIdx.x;
    if (i >= n4) return;
    float4 v = src[i];
    dh2[i * 2 + 0] = __floats2half2_rn(v.x, v.y);
    dh2[i * 2 + 1] = __floats2half2_rn(v.z, v.w);
}

// All weight transposes in one kernel. Segments (output [n][k] fp16):
//  [0, 32768)        wl0t  <- Wl0 [128][256]
//  [32768, 65536)    wr0t  <- Wr0
//  [65536, 131072)   wl1t  <- Wl1 [256][256]
//  [131072, 196608)  wr1t  <- Wr1
//  [196608, 229376)  wcatt <- [Wl2|Wr2] [256][64] each
__global__ void wt_all_kernel(const float* __restrict__ Wl0, const float* __restrict__ Wr0,
                              const float* __restrict__ Wl1, const float* __restrict__ Wr1,
                              const float* __restrict__ Wl2, const float* __restrict__ Wr2,
                              __half* __restrict__ wl0t, __half* __restrict__ wr0t,
                              __half* __restrict__ wl1t, __half* __restrict__ wr1t,
                              __half* __restrict__ wcatt) {
    int i = blockIdx.x * blockDim.x + threadIdx.x;
    if (i >= 229376) return;
    if (i < 65536) {
        int j = i & 32767;
        int n = j >> 7, k = j & 127;            // [256 n][128 k]
        const float* W = (i < 32768) ? Wl0 : Wr0;
        __half* Wt = (i < 32768) ? wl0t : wr0t;
        Wt[j] = __float2half_rn(W[k * HIDDIM + n]);
    } else if (i < 196608) {
        int j = (i - 65536) & 65535;
        int n = j >> 8, k = j & 255;            // [256 n][256 k]
        const float* W = (i < 131072) ? Wl1 : Wr1;
        __half* Wt = (i < 131072) ? wl1t : wr1t;
        Wt[j] = __float2half_rn(W[k * HIDDIM + n]);
    } else {
        int j = i - 196608;
        int n = j >> 8, k = j & 255;            // [128 n][256 k]
        float v = (n < 64) ? Wl2[k * 64 + n] : Wr2[k * 64 + (n - 64)];
        wcatt[j] = __float2half_rn(v);
    }
}

// ------------------ act (BN+ReLU) -> fp16 (gather + GEMM A) ------------------
__global__ void act_f16_kernel(const float4* __restrict__ H, __half2* __restrict__ O2,
                               int n4, const float* __restrict__ sc, const float* __restrict__ sh) {
    int i = blockIdx.x * blockDim.x + threadIdx.x;
    if (i >= n4) return;
    int c = (i * 4) & (HIDDIM - 1);
    float4 v = H[i];
    v.x = fmaxf(v.x * __ldg(sc + c + 0) + __ldg(sh + c + 0), 0.f);
    v.y = fmaxf(v.y * __ldg(sc + c + 1) + __ldg(sh + c + 1), 0.f);
    v.z = fmaxf(v.z * __ldg(sc + c + 2) + __ldg(sh + c + 2), 0.f);
    v.w = fmaxf(v.w * __ldg(sc + c + 3) + __ldg(sh + c + 3), 0.f);
    O2[i * 2 + 0] = __floats2half2_rn(v.x, v.y);
    O2[i * 2 + 1] = __floats2half2_rn(v.z, v.w);
}

// ------------------------- fp16 aggregation (D=256) --------------------------
__global__ void agg256_f16_kernel(const __half* __restrict__ Xh, __half* __restrict__ Out,
                                  const int* __restrict__ rowptr, const int* __restrict__ csr,
                                  const float* __restrict__ invdeg, int n_nodes) {
    int node = (blockIdx.x * blockDim.x + threadIdx.x) >> 5;
    if (node >= n_nodes) return;
    int lane = threadIdx.x & 31;
    int doff = lane * 8;

    float acc0[8], acc1[8];
#pragma unroll
    for (int i = 0; i < 8; i++) { acc0[i] = 0.f; acc1[i] = 0.f; }

    int beg = rowptr[node];
    int end = rowptr[node + 1];
    int e = beg;

    auto accum = [&](uint4 u, float* acc) {
        float2 f0 = __half22float2(*reinterpret_cast<__half2*>(&u.x));
        float2 f1 = __half22float2(*reinterpret_cast<__half2*>(&u.y));
        float2 f2 = __half22float2(*reinterpret_cast<__half2*>(&u.z));
        float2 f3 = __half22float2(*reinterpret_cast<__half2*>(&u.w));
        acc[0] += f0.x; acc[1] += f0.y;
        acc[2] += f1.x; acc[3] += f1.y;
        acc[4] += f2.x; acc[5] += f2.y;
        acc[6] += f3.x; acc[7] += f3.y;
    };

    for (; e + 3 < end; e += 4) {
        int s0 = __ldg(csr + e);
        int s1 = __ldg(csr + e + 1);
        int s2 = __ldg(csr + e + 2);
        int s3 = __ldg(csr + e + 3);
        uint4 u0 = __ldg(reinterpret_cast<const uint4*>(Xh + (size_t)s0 * HIDDIM + doff));
        uint4 u1 = __ldg(reinterpret_cast<const uint4*>(Xh + (size_t)s1 * HIDDIM + doff));
        uint4 u2 = __ldg(reinterpret_cast<const uint4*>(Xh + (size_t)s2 * HIDDIM + doff));
        uint4 u3 = __ldg(reinterpret_cast<const uint4*>(Xh + (size_t)s3 * HIDDIM + doff));
        accum(u0, acc0); accum(u1, acc1); accum(u2, acc0); accum(u3, acc1);
    }
    for (; e < end; e++) {
        int s0 = __ldg(csr + e);
        uint4 u0 = __ldg(reinterpret_cast<const uint4*>(Xh + (size_t)s0 * HIDDIM + doff));
        accum(u0, acc0);
    }

    float w = __ldg(invdeg + node);
    uint4 ov;
    __half2 h0 = __floats2half2_rn((acc0[0] + acc1[0]) * w, (acc0[1] + acc1[1]) * w);
    __half2 h1v = __floats2half2_rn((acc0[2] + acc1[2]) * w, (acc0[3] + acc1[3]) * w);
    __half2 h2v = __floats2half2_rn((acc0[4] + acc1[4]) * w, (acc0[5] + acc1[5]) * w);
    __half2 h3 = __floats2half2_rn((acc0[6] + acc1[6]) * w, (acc0[7] + acc1[7]) * w);
    ov.x = *reinterpret_cast<uint32_t*>(&h0);
    ov.y = *reinterpret_cast<uint32_t*>(&h1v);
    ov.z = *reinterpret_cast<uint32_t*>(&h2v);
    ov.w = *reinterpret_cast<uint32_t*>(&h3);
    *reinterpret_cast<uint4*>(Out + (size_t)node * HIDDIM + doff) = ov;
}

// ------------------------- fp16 aggregation (D=128) --------------------------
__global__ void agg128_f16_kernel(const __half* __restrict__ Xh, __half* __restrict__ Out,
                                  const int* __restrict__ rowptr, const int* __restrict__ csr,
                                  const float* __restrict__ invdeg, int n_nodes) {
    int node = (blockIdx.x * blockDim.x + threadIdx.x) >> 5;
    if (node >= n_nodes) return;
    int lane = threadIdx.x & 31;
    int doff = lane * 4;

    float acc0[4], acc1[4];
#pragma unroll
    for (int i = 0; i < 4; i++) { acc0[i] = 0.f; acc1[i] = 0.f; }

    int beg = rowptr[node];
    int end = rowptr[node + 1];
    int e = beg;

    auto accum = [&](uint2 u, float* acc) {
        float2 f0 = __half22float2(*reinterpret_cast<__half2*>(&u.x));
        float2 f1 = __half22float2(*reinterpret_cast<__half2*>(&u.y));
        acc[0] += f0.x; acc[1] += f0.y;
        acc[2] += f1.x; acc[3] += f1.y;
    };

    for (; e + 3 < end; e += 4) {
        int s0 = __ldg(csr + e);
        int s1 = __ldg(csr + e + 1);
        int s2 = __ldg(csr + e + 2);
        int s3 = __ldg(csr + e + 3);
        uint2 u0 = __ldg(reinterpret_cast<const uint2*>(Xh + (size_t)s0 * INDIM + doff));
        uint2 u1 = __ldg(reinterpret_cast<const uint2*>(Xh + (size_t)s1 * INDIM + doff));
        uint2 u2 = __ldg(reinterpret_cast<const uint2*>(Xh + (size_t)s2 * INDIM + doff));
        uint2 u3 = __ldg(reinterpret_cast<const uint2*>(Xh + (size_t)s3 * INDIM + doff));
        accum(u0, acc0); accum(u1, acc1); accum(u2, acc0); accum(u3, acc1);
    }
    for (; e < end; e++) {
        int s0 = __ldg(csr + e);
        uint2 u0 = __ldg(reinterpret_cast<const uint2*>(Xh + (size_t)s0 * INDIM + doff));
        accum(u0, acc0);
    }

    float w = __ldg(invdeg + node);
    __half2 h0 = __floats2half2_rn((acc0[0] + acc1[0]) * w, (acc0[1] + acc1[1]) * w);
    __half2 h1v = __floats2half2_rn((acc0[2] + acc1[2]) * w, (acc0[3] + acc1[3]) * w);
    uint2 ov;
    ov.x = *reinterpret_cast<uint32_t*>(&h0);
    ov.y = *reinterpret_cast<uint32_t*>(&h1v);
    *reinterpret_cast<uint2*>(Out + (size_t)node * INDIM + doff) = ov;
}

// ------------------------- fp16 aggregation (D=64, ADD) ----------------------
__global__ void agg64_f16_kernel(const __half* __restrict__ Yh, float* __restrict__ Out,
                                 const int* __restrict__ rowptr, const int* __restrict__ csr,
                                 const float* __restrict__ invdeg, int n_nodes) {
    int node = (blockIdx.x * blockDim.x + threadIdx.x) >> 5;
    if (node >= n_nodes) return;
    int lane = threadIdx.x & 31;
    int doff = lane * 2;

    float a0 = 0.f, a1 = 0.f, b0 = 0.f, b1 = 0.f;

    int beg = rowptr[node];
    int end = rowptr[node + 1];
    int e = beg;

    for (; e + 3 < end; e += 4) {
        int s0 = __ldg(csr + e);
        int s1 = __ldg(csr + e + 1);
        int s2 = __ldg(csr + e + 2);
        int s3 = __ldg(csr + e + 3);
        float2 f0 = __half22float2(*reinterpret_cast<const __half2*>(Yh + (size_t)s0 * OUTDIM + doff));
        float2 f1 = __half22float2(*reinterpret_cast<const __half2*>(Yh + (size_t)s1 * OUTDIM + doff));
        float2 f2 = __half22float2(*reinterpret_cast<const __half2*>(Yh + (size_t)s2 * OUTDIM + doff));
        float2 f3 = __half22float2(*reinterpret_cast<const __half2*>(Yh + (size_t)s3 * OUTDIM + doff));
        a0 += f0.x + f2.x;  b0 += f1.x + f3.x;
        a1 += f0.y + f2.y;  b1 += f1.y + f3.y;
    }
    for (; e < end; e++) {
        int s0 = __ldg(csr + e);
        float2 f0 = __half22float2(*reinterpret_cast<const __half2*>(Yh + (size_t)s0 * OUTDIM + doff));
        a0 += f0.x; a1 += f0.y;
    }

    float w = __ldg(invdeg + node);
    float* o = Out + (size_t)node * OUTDIM + doff;
    o[0] += (a0 + b0) * w;
    o[1] += (a1 + b1) * w;
}

// ------------------------------ FP16 GEMM v4 ---------------------------------
__device__ __forceinline__ void mma_f16(float c[4], const unsigned a[4], const unsigned b[2]) {
    asm volatile(
        "mma.sync.aligned.m16n8k16.row.col.f32.f16.f16.f32 "
        "{%0,%1,%2,%3}, {%4,%5,%6,%7}, {%8,%9}, {%0,%1,%2,%3};"
        : "+f"(c[0]), "+f"(c[1]), "+f"(c[2]), "+f"(c[3])
        : "r"(a[0]), "r"(a[1]), "r"(a[2]), "r"(a[3]), "r"(b[0]), "r"(b[1]));
}

// C = A0@B0t^T (+ A1@B1t^T) (+ bias). fp16 in, fp32 accumulate.
// Sp/Sq non-null: fused column stats (sum / sum-sq of stored C values) written
// as deterministic partials Sp[blockIdx.y * N + col].
// Split mode (Cy != null, N==128): cols [0,64) -> Cy fp16, [64,128) -> C+bias.
template <int BM, int BN, int WM, int WN>
__global__ void __launch_bounds__(256, 2)
gemm_f16(const __half* __restrict__ A0, const __half* __restrict__ B0t,
         const __half* __restrict__ A1, const __half* __restrict__ B1t,
         float* __restrict__ C, __half* __restrict__ Cy,
         int M, int N, int K, const float* __restrict__ bias,
         float* __restrict__ Sp, float* __restrict__ Sq) {
    constexpr int BK = 32, THREADS = 256;
    constexpr int WCOLS = BN / WN;
    constexpr int MT = WM / 16, NT = WN / 8;
    constexpr int AST = BK + 8;
    constexpr int BST = BK + 8;
    constexpr int ACH = (BM * BK) / (8 * THREADS);
    constexpr int BCH = (BN * BK) / (8 * THREADS);
    constexpr int ABUF = BM * AST;
    constexpr int BBUF = BN * BST;
    static_assert((BM / WM) * (BN / WN) == 8, "8 warps");

    __shared__ __half Asm[2 * ABUF];
    __shared__ __half Bsm[2 * BBUF];
    __shared__ float sstat[2][2][BN];   // [wrow][sum|sq][col]

    int tid = threadIdx.x, lane = tid & 31, warp = tid >> 5;
    int wrow = warp / WCOLS, wcol = warp % WCOLS;
    int block_m = blockIdx.y * BM, block_n = blockIdx.x * BN;
    int g = lane >> 2, q = lane & 3;

    uint32_t AsmAddr = (uint32_t)__cvta_generic_to_shared(Asm);
    uint32_t BsmAddr = (uint32_t)__cvta_generic_to_shared(Bsm);

    float acc[MT][NT][4];
#pragma unroll
    for (int mt = 0; mt < MT; mt++)
#pragma unroll
        for (int nt = 0; nt < NT; nt++)
#pragma unroll
            for (int r = 0; r < 4; r++) acc[mt][nt][r] = 0.0f;

    const int kiters = K / BK;
    const int npass = A1 ? 2 : 1;
    const int total = npass * kiters;

    auto issue_stage = [&](int it, int buf) {
        int pass = it / kiters;
        int k0 = (it - pass * kiters) * BK;
        const __half* Ap = pass ? A1 : A0;
        const __half* Bp = pass ? B1t : B0t;
#pragma unroll
        for (int i = 0; i < ACH; i++) {
            int chunk = tid + i * THREADS;
            int r = chunk >> 2;
            int c8 = (chunk & 3) << 3;
            int gr = block_m + r;
            uint32_t dst = AsmAddr + (buf * ABUF + r * AST + c8) * 2;
            cp_async16(dst, Ap + (size_t)gr * K + k0 + c8, gr < M);
        }
#pragma unroll
        for (int i = 0; i < BCH; i++) {
            int chunk = tid + i * THREADS;
            int r = chunk >> 2;
            int c8 = (chunk & 3) << 3;
            uint32_t dst = BsmAddr + (buf * BBUF + r * BST + c8) * 2;
            cp_async16(dst, Bp + (size_t)(block_n + r) * K + k0 + c8, true);
        }
        cp_commit();
    };

    issue_stage(0, 0);
    int buf = 0;
    for (int it = 0; it < total; ++it) {
        cp_wait0();
        __syncthreads();
        if (it + 1 < total) issue_stage(it + 1, buf ^ 1);

        const __half* Ab = Asm + buf * ABUF;
        const __half* Bb = Bsm + buf * BBUF;
#pragma unroll
        for (int s = 0; s < BK / 16; ++s) {
            int kb = s * 16 + q * 2;
            unsigned af[MT][4], bf[NT][2];
#pragma unroll
            for (int mt = 0; mt < MT; ++mt) {
                int m = wrow * WM + mt * 16 + g;
                af[mt][0] = *reinterpret_cast<const unsigned*>(Ab + m * AST + kb);
                af[mt][1] = *reinterpret_cast<const unsigned*>(Ab + (m + 8) * AST + kb);
                af[mt][2] = *reinterpret_cast<const unsigned*>(Ab + m * AST + kb + 8);
                af[mt][3] = *reinterpret_cast<const unsigned*>(Ab + (m + 8) * AST + kb + 8);
            }
#pragma unroll
            for (int nt = 0; nt < NT; ++nt) {
                int nn = wcol * WN + nt * 8 + g;
                bf[nt][0] = *reinterpret_cast<const unsigned*>(Bb + nn * BST + kb);
                bf[nt][1] = *reinterpret_cast<const unsigned*>(Bb + nn * BST + kb + 8);
            }
#pragma unroll
            for (int mt = 0; mt < MT; ++mt)
#pragma unroll
                for (int nt = 0; nt < NT; ++nt)
                    mma_f16(acc[mt][nt], af[mt], bf[nt]);
        }
        buf ^= 1;
    }

    float csum[NT][2], csq[NT][2];
#pragma unroll
    for (int nt = 0; nt < NT; nt++) {
        csum[nt][0] = csum[nt][1] = 0.f;
        csq[nt][0]  = csq[nt][1]  = 0.f;
    }

#pragma unroll
    for (int mt = 0; mt < MT; ++mt) {
        int r0 = block_m + wrow * WM + mt * 16 + g;
        int r1 = r0 + 8;
#pragma unroll
        for (int nt = 0; nt < NT; ++nt) {
            int cn = block_n + wcol * WN + nt * 8 + q * 2;
            if (Cy) {
                if (cn < 64) {
                    if (r0 < M)
                        *reinterpret_cast<__half2*>(Cy + (size_t)r0 * 64 + cn) =
                            __floats2half2_rn(acc[mt][nt][0], acc[mt][nt][1]);
                    if (r1 < M)
                        *reinterpret_cast<__half2*>(Cy + (size_t)r1 * 64 + cn) =
                            __floats2half2_rn(acc[mt][nt][2], acc[mt][nt][3]);
                } else {
                    int co = cn - 64;
                    float b0 = __ldg(bias + co), b1 = __ldg(bias + co + 1);
                    if (r0 < M) {
                        float2 t0 = make_float2(acc[mt][nt][0] + b0, acc[mt][nt][1] + b1);
                        *reinterpret_cast<float2*>(C + (size_t)r0 * 64 + co) = t0;
                    }
                    if (r1 < M) {
                        float2 t1 = make_float2(acc[mt][nt][2] + b0, acc[mt][nt][3] + b1);
                        *reinterpret_cast<float2*>(C + (size_t)r1 * 64 + co) = t1;
                    }
                }
            } else {
                float b0 = 0.f, b1 = 0.f;
                if (bias) { b0 = __ldg(bias + cn); b1 = __ldg(bias + cn + 1); }
                if (r0 < M) {
                    float2 t0 = make_float2(acc[mt][nt][0] + b0, acc[mt][nt][1] + b1);
                    *reinterpret_cast<float2*>(C + (size_t)r0 * N + cn) = t0;
                    if (Sp) {
                        csum[nt][0] += t0.x;        csum[nt][1] += t0.y;
                        csq[nt][0]  += t0.x * t0.x; csq[nt][1]  += t0.y * t0.y;
                    }
                }
                if (r1 < M) {
                    float2 t1 = make_float2(acc[mt][nt][2] + b0, acc[mt][nt][3] + b1);
                    *reinterpret_cast<float2*>(C + (size_t)r1 * N + cn) = t1;
                    if (Sp) {
                        csum[nt][0] += t1.x;        csum[nt][1] += t1.y;
                        csq[nt][0]  += t1.x * t1.x; csq[nt][1]  += t1.y * t1.y;
                    }
                }
            }
        }
    }

    // Fused column-stats: reduce over g (lanes stride 4), combine wrow halves.
    if (Sp) {
#pragma unroll
        for (int nt = 0; nt < NT; nt++)
#pragma unroll
            for (int c = 0; c < 2; c++) {
                float s = csum[nt][c], sq = csq[nt][c];
#pragma unroll
                for (int off = 16; off >= 4; off >>= 1) {
                    s  += __shfl_down_sync(0xffffffffu, s,  off);
                    sq += __shfl_down_sync(0xffffffffu, sq, off);
                }
                if (lane < 4) {   // g == 0; lane == q
                    int col = wcol * WN + nt * 8 + lane * 2 + c;
                    sstat[wrow][0][col] = s;
                    sstat[wrow][1][col] = sq;
                }
            }
        __syncthreads();
        if (tid < BN) {
            size_t o = (size_t)blockIdx.y * N + block_n + tid;
            Sp[o] = sstat[0][0][tid] + sstat[1][0][tid];
            Sq[o] = sstat[0][1][tid] + sstat[1][1][tid];
        }
    }
}

// ------------------------------- BatchNorm ----------------------------------
__global__ void colstats_final(const float* __restrict__ ps, const float* __restrict__ pq,
                               int nb, float inv_m,
                               const float* __restrict__ g, const float* __restrict__ be,
                               float* __restrict__ scale, float* __restrict__ shift) {
    int c = threadIdx.x;
    float s = 0.f, q = 0.f;
    for (int b = 0; b < nb; b++) {
        s += ps[b * HIDDIM + c];
        q += pq[b * HIDDIM + c];
    }
    float mu  = s * inv_m;
    float var = q * inv_m - mu * mu;
    float rs  = rsqrtf(var + 1e-5f);
    float sc  = g[c] * rs;
    scale[c] = sc;
    shift[c] = be[c] - mu * sc;
}

// --------------------------------- launch -----------------------------------
extern "C" void kernel_launch(void* const* d_in, const int* in_sizes, int n_in,
                              void* d_out, int out_size) {
    const float* x   = (const float*)d_in[0];
    const int*   ei  = (const int*)d_in[1];
    const float* Wl0 = (const float*)d_in[2];
    const float* bl0 = (const float*)d_in[3];
    const float* Wr0 = (const float*)d_in[4];
    const float* Wl1 = (const float*)d_in[5];
    const float* bl1 = (const float*)d_in[6];
    const float* Wr1 = (const float*)d_in[7];
    const float* Wl2 = (const float*)d_in[8];
    const float* bl2 = (const float*)d_in[9];
    const float* Wr2 = (const float*)d_in[10];
    const float* g0  = (const float*)d_in[11];
    const float* be0 = (const float*)d_in[12];
    const float* g1  = (const float*)d_in[13];
    const float* be1 = (const float*)d_in[14];
    float* out = (float*)d_out;

    const int N  = NNODES;
    const int NE = NEDGES;

    float *h1, *h2, *invdeg, *ps, *pq, *scale, *shift;
    __half *aggh, *xh, *h1h, *h2h, *yh, *wl0t, *wr0t, *wl1t, *wr1t, *wcatt;
    int *cnt, *rowptr, *fill, *csr, *bsum;
    cudaGetSymbolAddress((void**)&h1,     g_h1);
    cudaGetSymbolAddress((void**)&h2,     g_h2);
    cudaGetSymbolAddress((void**)&aggh,   g_aggh);
    cudaGetSymbolAddress((void**)&xh,     g_xh);
    cudaGetSymbolAddress((void**)&h1h,    g_h1h);
    cudaGetSymbolAddress((void**)&h2h,    g_h2h);
    cudaGetSymbolAddress((void**)&yh,     g_yh);
    cudaGetSymbolAddress((void**)&wl0t,   g_wl0t);
    cudaGetSymbolAddress((void**)&wr0t,   g_wr0t);
    cudaGetSymbolAddress((void**)&wl1t,   g_wl1t);
    cudaGetSymbolAddress((void**)&wr1t,   g_wr1t);
    cudaGetSymbolAddress((void**)&wcatt,  g_wcatt);
    cudaGetSymbolAddress((void**)&invdeg, g_invdeg);
    cudaGetSymbolAddress((void**)&cnt,    g_cnt);
    cudaGetSymbolAddress((void**)&rowptr, g_rowptr);
    cudaGetSymbolAddress((void**)&fill,   g_fill);
    cudaGetSymbolAddress((void**)&csr,    g_csr);
    cudaGetSymbolAddress((void**)&bsum,   g_bsum);
    cudaGetSymbolAddress((void**)&ps,     g_ps);
    cudaGetSymbolAddress((void**)&pq,     g_pq);
    cudaGetSymbolAddress((void**)&scale,  g_scale);
    cudaGetSymbolAddress((void**)&shift,  g_shift);

    dim3 gridBig(HIDDIM / 128, (N + 127) / 128);    // N=256 -> grid.x 2
    dim3 gridL2(1, (N + 127) / 128);                // fused layer-2: N=128
    const int AGG_BLOCKS = (N + 7) / 8;

    // ---- CSR build (3-phase scan) + prologue ----
    zero_int_kernel<<<(N + 255) / 256, 256>>>(cnt, N);
    hist_kernel<<<(NE + 255) / 256, 256>>>(ei, NE, cnt);
    scan_bsums_kernel<<<NBLK, 256>>>(cnt, bsum, N);
    scan_offsets_kernel<<<1, 256>>>(bsum, NBLK);
    scan_final_kernel<<<NBLK, 256>>>(cnt, bsum, rowptr, fill, invdeg, N);
    scatter_kernel<<<(NE + 255) / 256, 256>>>(ei, NE, fill, csr);
    x_f16_kernel<<<(N * INDIM / 4 + 255) / 256, 256>>>((const float4*)x, (__half2*)xh, N * INDIM / 4);
    wt_all_kernel<<<(229376 + 255) / 256, 256>>>(Wl0, Wr0, Wl1, Wr1, Wl2, Wr2,
                                                 wl0t, wr0t, wl1t, wr1t, wcatt);

    // ---- Layer 0: h1 = mean_agg(x) @ Wl0 + x @ Wr0 + bl0  (+ fused stats) ----
    agg128_f16_kernel<<<AGG_BLOCKS, 256>>>(xh, aggh, rowptr, csr, invdeg, N);
    gemm_f16<128, 128, 64, 32><<<gridBig, 256>>>(
        aggh, wl0t, xh, wr0t, h1, nullptr, N, HIDDIM, INDIM, bl0, ps, pq);
    colstats_final<<<1, HIDDIM>>>(ps, pq, NBY, 1.0f / (float)N, g0, be0, scale, shift);

    // ---- Layer 1: h2 = mean_agg(act0(h1)) @ Wl1 + act0(h1) @ Wr1 + bl1 ----
    act_f16_kernel<<<(N * HIDDIM / 4 + 255) / 256, 256>>>(
        (const float4*)h1, (__half2*)h1h, N * HIDDIM / 4, scale, shift);
    agg256_f16_kernel<<<AGG_BLOCKS, 256>>>(h1h, aggh, rowptr, csr, invdeg, N);
    gemm_f16<128, 128, 64, 32><<<gridBig, 256>>>(
        aggh, wl1t, h1h, wr1t, h2, nullptr, N, HIDDIM, HIDDIM, bl1, ps, pq);
    colstats_final<<<1, HIDDIM>>>(ps, pq, NBY, 1.0f / (float)N, g1, be1, scale, shift);

    // ---- Layer 2 (fused): [y | out] = act1(h2) @ [Wl2 | Wr2]; y fp16 ----
    act_f16_kernel<<<(N * HIDDIM / 4 + 255) / 256, 256>>>(
        (const float4*)h2, (__half2*)h2h, N * HIDDIM / 4, scale, shift);
    gemm_f16<128, 128, 64, 32><<<gridL2, 256>>>(
        h2h, wcatt, nullptr, nullptr, out, yh, N, 128, HIDDIM, bl2, nullptr, nullptr);
    agg64_f16_kernel<<<AGG_BLOCKS, 256>>>(yh, out, rowptr, csr, invdeg, N);
}